// round 7
// baseline (speedup 1.0000x reference)
#include <cuda_runtime.h>
#include <cuda_bf16.h>
#include <math.h>

#define BB 16
#define NNP 2048
#define IND 64
#define HD 128
#define NOBJ 8
#define NSLOT 24
#define NITER 3

// ---------------- device scratch (static, no allocation) ----------------
__device__ float g_hyp[BB*NNP*HD];
__device__ float g_feats[BB*NNP*HD];
__device__ float g_x2[BB*NNP];
__device__ float g_f2[BB*NNP];
__device__ float g_fr[BB*NNP];
__device__ float g_density[BB*NNP];
__device__ float g_slots[BB*NSLOT*HD];
__device__ float g_s2[BB*NSLOT];
__device__ float g_sr[BB*NSLOT];
__device__ float g_gh[NOBJ*3*HD];
__device__ float g_upd[BB*NSLOT*HD];
__device__ float g_rowsum[BB*NSLOT];
__device__ __nv_bfloat162 g_xbf2[BB*NNP*IND/2];   // x in bf16 (density path only)

__device__ __forceinline__ float geluf(float x){
    return 0.5f*x*(1.f+erff(x*0.70710678118654752f));
}
__device__ __forceinline__ float sigmoidf(float x){
    return 1.f/(1.f+expf(-x));
}

// ======================= encoder v3: all weights resident, 64 tokens/block =======================
// 256 threads = 8 warps, each warp owns 8 tokens. W1+W2+W3 stay in smem (160KB) for the
// whole block -> weight L2 traffic drops 16x (1.31GB -> 82MB). s_h rows are warp-private,
// so inter-stage syncs are __syncwarp only.
#define ENC_SMEM_FLOATS (IND*HD + HD*HD + HD*HD + 64*IND + 64*HD)   // 53248 floats = 212992 B

__global__ void __launch_bounds__(256) enc_kernel(const float* __restrict__ x,
    const float* __restrict__ fe_w1, const float* __restrict__ fe_b1,
    const float* __restrict__ ln1_g, const float* __restrict__ ln1_b,
    const float* __restrict__ fe_w2, const float* __restrict__ fe_b2,
    const float* __restrict__ ln2_g, const float* __restrict__ ln2_b,
    const float* __restrict__ hp_w,  const float* __restrict__ hp_b)
{
    extern __shared__ float sm[];
    float* s_w1 = sm;                       // 64*128
    float* s_w2 = s_w1 + IND*HD;            // 128*128
    float* s_w3 = s_w2 + HD*HD;             // 128*128
    float* s_x  = s_w3 + HD*HD;             // 64*64
    float* s_h  = s_x  + 64*IND;            // 64*128

    const int tid = threadIdx.x;
    const int tokbase = blockIdx.x*64;
    {
        const float4* a=(const float4*)fe_w1; float4* d1=(float4*)s_w1;
        for (int i=tid;i<IND*HD/4;i+=256) d1[i]=a[i];
        const float4* b=(const float4*)fe_w2; float4* d2=(float4*)s_w2;
        for (int i=tid;i<HD*HD/4;i+=256) d2[i]=b[i];
        const float4* c=(const float4*)hp_w; float4* d3=(float4*)s_w3;
        for (int i=tid;i<HD*HD/4;i+=256) d3[i]=c[i];
        const float4* xs=(const float4*)(x + (size_t)tokbase*IND); float4* xd=(float4*)s_x;
        for (int i=tid;i<64*IND/4;i+=256) xd[i]=xs[i];
    }
    __syncthreads();
    if (tid < 64){
        float s=0.f;
        #pragma unroll 8
        for (int k=0;k<IND;k++){ float v=s_x[tid*IND+k]; s+=v*v; }
        g_x2[tokbase+tid]=s;
    }
    const int w = tid>>5, l = tid&31;

    float acc[8][4];
    // ---- stage A: h1 = gelu(LN(x@W1+b1)) ----
    #pragma unroll
    for (int t=0;t<8;t++){acc[t][0]=acc[t][1]=acc[t][2]=acc[t][3]=0.f;}
    {
        const float4* w4=(const float4*)s_w1;
        for (int k=0;k<IND;k++){
            float4 wv = w4[k*32+l];
            #pragma unroll
            for (int t=0;t<8;t++){
                float xv = s_x[(w*8+t)*IND + k];
                acc[t][0]=fmaf(xv,wv.x,acc[t][0]); acc[t][1]=fmaf(xv,wv.y,acc[t][1]);
                acc[t][2]=fmaf(xv,wv.z,acc[t][2]); acc[t][3]=fmaf(xv,wv.w,acc[t][3]);
            }
        }
    }
    {
        float4 bv=((const float4*)fe_b1)[l];
        float4 gv=((const float4*)ln1_g)[l];
        float4 bt=((const float4*)ln1_b)[l];
        #pragma unroll
        for (int t=0;t<8;t++){
            float v0=acc[t][0]+bv.x, v1=acc[t][1]+bv.y, v2=acc[t][2]+bv.z, v3=acc[t][3]+bv.w;
            float s=v0+v1+v2+v3, q=v0*v0+v1*v1+v2*v2+v3*v3;
            #pragma unroll
            for (int o=16;o;o>>=1){ s+=__shfl_xor_sync(0xffffffffu,s,o); q+=__shfl_xor_sync(0xffffffffu,q,o); }
            float mu=s*(1.f/HD), var=q*(1.f/HD)-mu*mu;
            float inv=rsqrtf(var+1e-5f);
            v0=geluf((v0-mu)*inv*gv.x+bt.x); v1=geluf((v1-mu)*inv*gv.y+bt.y);
            v2=geluf((v2-mu)*inv*gv.z+bt.z); v3=geluf((v3-mu)*inv*gv.w+bt.w);
            float4* hv=(float4*)&s_h[(w*8+t)*HD + l*4];
            *hv = make_float4(v0,v1,v2,v3);
        }
    }
    __syncwarp();
    // ---- stage B: enc = LN(h1@W2+b2) ----
    #pragma unroll
    for (int t=0;t<8;t++){acc[t][0]=acc[t][1]=acc[t][2]=acc[t][3]=0.f;}
    {
        const float4* w4=(const float4*)s_w2;
        for (int k=0;k<HD;k++){
            float4 wv = w4[k*32+l];
            #pragma unroll
            for (int t=0;t<8;t++){
                float xv = s_h[(w*8+t)*HD + k];
                acc[t][0]=fmaf(xv,wv.x,acc[t][0]); acc[t][1]=fmaf(xv,wv.y,acc[t][1]);
                acc[t][2]=fmaf(xv,wv.z,acc[t][2]); acc[t][3]=fmaf(xv,wv.w,acc[t][3]);
            }
        }
    }
    {
        float4 bv=((const float4*)fe_b2)[l];
        float4 gv=((const float4*)ln2_g)[l];
        float4 bt=((const float4*)ln2_b)[l];
        #pragma unroll
        for (int t=0;t<8;t++){
            float v0=acc[t][0]+bv.x, v1=acc[t][1]+bv.y, v2=acc[t][2]+bv.z, v3=acc[t][3]+bv.w;
            float s=v0+v1+v2+v3, q=v0*v0+v1*v1+v2*v2+v3*v3;
            #pragma unroll
            for (int o=16;o;o>>=1){ s+=__shfl_xor_sync(0xffffffffu,s,o); q+=__shfl_xor_sync(0xffffffffu,q,o); }
            float mu=s*(1.f/HD), var=q*(1.f/HD)-mu*mu;
            float inv=rsqrtf(var+1e-5f);
            acc[t][0]=(v0-mu)*inv*gv.x+bt.x; acc[t][1]=(v1-mu)*inv*gv.y+bt.y;
            acc[t][2]=(v2-mu)*inv*gv.z+bt.z; acc[t][3]=(v3-mu)*inv*gv.w+bt.w;
        }
    }
    __syncwarp();
    #pragma unroll
    for (int t=0;t<8;t++){
        float4* hv=(float4*)&s_h[(w*8+t)*HD + l*4];
        *hv = make_float4(acc[t][0],acc[t][1],acc[t][2],acc[t][3]);
    }
    __syncwarp();
    // ---- stage C: hyp = tanh(enc@hp_w + hp_b) ----
    #pragma unroll
    for (int t=0;t<8;t++){acc[t][0]=acc[t][1]=acc[t][2]=acc[t][3]=0.f;}
    {
        const float4* w4=(const float4*)s_w3;
        for (int k=0;k<HD;k++){
            float4 wv = w4[k*32+l];
            #pragma unroll
            for (int t=0;t<8;t++){
                float xv = s_h[(w*8+t)*HD + k];
                acc[t][0]=fmaf(xv,wv.x,acc[t][0]); acc[t][1]=fmaf(xv,wv.y,acc[t][1]);
                acc[t][2]=fmaf(xv,wv.z,acc[t][2]); acc[t][3]=fmaf(xv,wv.w,acc[t][3]);
            }
        }
    }
    {
        float4 bv=((const float4*)hp_b)[l];
        #pragma unroll
        for (int t=0;t<8;t++){
            float4 hv;
            hv.x=tanhf(acc[t][0]+bv.x); hv.y=tanhf(acc[t][1]+bv.y);
            hv.z=tanhf(acc[t][2]+bv.z); hv.w=tanhf(acc[t][3]+bv.w);
            ((float4*)(g_hyp + (size_t)(tokbase + w*8 + t)*HD))[l]=hv;
        }
    }
}

// ======================= x -> bf16 prep =======================
__global__ void xbf_kernel(const float* __restrict__ x)
{
    int i = blockIdx.x*256 + threadIdx.x;           // BB*NNP*IND/2 pairs
    float2 v = ((const float2*)x)[i];
    g_xbf2[i] = __float22bfloat162_rn(v);
}

// ======================= density: bf16 mma.sync gram + top-6 (unchanged from R6) =======================
__device__ __forceinline__ void ins6(float t[6], float v){
    if (v < t[5]){
        t[5]=v;
        #pragma unroll
        for (int s=5;s>0;s--){ if (t[s]<t[s-1]){ float tmp=t[s-1]; t[s-1]=t[s]; t[s]=tmp; } }
    }
}

#define JT_STRIDE 72

__global__ void __launch_bounds__(256) dens_kernel(float* __restrict__ dens_out)
{
    __shared__ float smf[3200];
    __nv_bfloat16* sxj = (__nv_bfloat16*)smf;
    float* x2s  = smf + (64*JT_STRIDE*2)/4;
    float* cand = smf;

    const int b  = blockIdx.y;
    const int i0 = blockIdx.x * 64;
    const int tid = threadIdx.x, w = tid>>5, lane = tid&31;
    const int g = lane>>2, tg = lane&3;
    const int rg = w & 3;
    const int jh = w >> 2;
    const int r0 = i0 + rg*16 + g;
    const unsigned short* xb = (const unsigned short*)g_xbf2 + (size_t)b*NNP*IND;

    unsigned int A[4][4];
    {
        const unsigned short* xr0 = xb + (size_t)r0*IND;
        const unsigned short* xr1 = xr0 + 8*IND;
        #pragma unroll
        for (int ks=0;ks<4;ks++){
            int kb = ks*16 + tg*2;
            A[ks][0] = *(const unsigned int*)&xr0[kb];
            A[ks][1] = *(const unsigned int*)&xr1[kb];
            A[ks][2] = *(const unsigned int*)&xr0[kb+8];
            A[ks][3] = *(const unsigned int*)&xr1[kb+8];
        }
    }
    float t6[2][6];
    #pragma unroll
    for (int r=0;r<2;r++){
        #pragma unroll
        for (int s=0;s<6;s++) t6[r][s]=1e30f;
    }

    for (int jt=0; jt<32; jt++){
        __syncthreads();
        {
            #pragma unroll
            for (int p=0;p<8;p++){
                int idx = tid + 256*p;
                int row = idx >> 5, c = idx & 31;
                unsigned int v = *(const unsigned int*)&xb[((size_t)(jt*64 + row))*IND + c*2];
                *(unsigned int*)&sxj[row*JT_STRIDE + c*2] = v;
            }
            if (tid < 64) x2s[tid] = g_x2[b*NNP + jt*64 + tid];
        }
        __syncthreads();
        #pragma unroll
        for (int q=0;q<4;q++){
            const int nt = jh*4 + q;
            const int n  = nt*8 + g;
            float c0=0.f,c1=0.f,c2=0.f,c3=0.f;
            #pragma unroll
            for (int ks=0;ks<4;ks++){
                const __nv_bfloat16* bp = &sxj[n*JT_STRIDE + ks*16 + tg*2];
                unsigned int B0 = *(const unsigned int*)bp;
                unsigned int B1 = *(const unsigned int*)(bp+8);
                asm("mma.sync.aligned.m16n8k16.row.col.f32.bf16.bf16.f32 "
                    "{%0,%1,%2,%3}, {%4,%5,%6,%7}, {%8,%9}, {%0,%1,%2,%3};"
                    : "+f"(c0),"+f"(c1),"+f"(c2),"+f"(c3)
                    : "r"(A[ks][0]),"r"(A[ks][1]),"r"(A[ks][2]),"r"(A[ks][3]),
                      "r"(B0),"r"(B1));
            }
            const int lc = nt*8 + tg*2;
            float xa = x2s[lc], xc = x2s[lc+1];
            ins6(t6[0], xa - 2.f*c0); ins6(t6[0], xc - 2.f*c1);
            ins6(t6[1], xa - 2.f*c2); ins6(t6[1], xc - 2.f*c3);
        }
    }
    __syncthreads();
    {
        int lr0 = rg*16 + g;
        int base = jh*24 + tg*6;
        #pragma unroll
        for (int s=0;s<6;s++){
            cand[lr0*49 + base + s]     = t6[0][s];
            cand[(lr0+8)*49 + base + s] = t6[1][s];
        }
    }
    __syncthreads();
    if (tid < 64){
        float u[6]={1e30f,1e30f,1e30f,1e30f,1e30f,1e30f};
        const float* row = &cand[tid*49];
        #pragma unroll 8
        for (int m=0;m<48;m++) ins6(u, row[m]);
        float x2i = g_x2[b*NNP + i0 + tid];
        float md = (sqrtf(fmaxf(x2i+u[1],0.f)) + sqrtf(fmaxf(x2i+u[2],0.f))
                  + sqrtf(fmaxf(x2i+u[3],0.f)) + sqrtf(fmaxf(x2i+u[4],0.f))
                  + sqrtf(fmaxf(x2i+u[5],0.f))) * 0.2f;
        float dv = tanhf(md);
        g_density[b*NNP + i0 + tid] = dv;
        dens_out [b*NNP + i0 + tid] = dv;
    }
}

// ======================= feats: Poincare projection =======================
__global__ void feats_kernel()
{
    const int w = threadIdx.x>>5, l = threadIdx.x&31;
    const int n = blockIdx.x*8 + w;
    float4 v = ((const float4*)(g_hyp + (size_t)n*HD))[l];
    float q = v.x*v.x+v.y*v.y+v.z*v.z+v.w*v.w;
    #pragma unroll
    for (int o=16;o;o>>=1) q += __shfl_xor_sync(0xffffffffu,q,o);
    float fn = fmaxf(sqrtf(q),1e-6f);
    float dens = g_density[n];
    float tr = (0.3f+0.5f*(1.f-dens))*0.95f;
    float sc = tr/fn;
    float4 f = make_float4(v.x*sc,v.y*sc,v.z*sc,v.w*sc);
    ((float4*)(g_feats + (size_t)n*HD))[l]=f;
    if (l==0){
        float f2=q*sc*sc;
        g_f2[n]=f2; g_fr[n]=sqrtf(f2);
    }
}

// ======================= slots init =======================
__global__ void slots_init_kernel(const float* __restrict__ obj_dirs)
{
    const int w=threadIdx.x>>5, l=threadIdx.x&31;
    if (w<NOBJ){
        float4 v=((const float4*)(obj_dirs + w*HD))[l];
        float q=v.x*v.x+v.y*v.y+v.z*v.z+v.w*v.w;
        #pragma unroll
        for (int o=16;o;o>>=1) q += __shfl_xor_sync(0xffffffffu,q,o);
        float nrm=sqrtf(q);
        float inv=1.f/fmaxf(nrm,1e-12f);
        float4 dn=make_float4(v.x*inv,v.y*inv,v.z*inv,v.w*inv);
        float qn=q*inv*inv;
        const float radii[3]={0.2f,0.5f,0.8f};
        for (int b=0;b<BB;b++){
            #pragma unroll
            for (int lv=0;lv<3;lv++){
                float r=radii[lv];
                ((float4*)(g_slots + (size_t)(b*NSLOT + w*3+lv)*HD))[l] =
                    make_float4(dn.x*r,dn.y*r,dn.z*r,dn.w*r);
                if (l==0){
                    float s2=qn*r*r;
                    g_s2[b*NSLOT + w*3+lv]=s2;
                    g_sr[b*NSLOT + w*3+lv]=sqrtf(s2);
                }
            }
        }
    }
}

// ======================= gh precompute =======================
__global__ void gh_kernel(const float* __restrict__ obj_dirs,
                          const float* __restrict__ gru_wh,
                          const float* __restrict__ gru_bh)
{
    const int o = blockIdx.x;
    const int w = threadIdx.x>>5, l = threadIdx.x&31;
    float4 od = ((const float4*)(obj_dirs + (size_t)o*HD))[l];
    for (int m=0;m<48;m++){
        int r = w*48 + m;
        float4 wv = ((const float4*)(gru_wh + (size_t)r*HD))[l];
        float p = od.x*wv.x + od.y*wv.y + od.z*wv.z + od.w*wv.w;
        #pragma unroll
        for (int of=16;of;of>>=1) p += __shfl_xor_sync(0xffffffffu,p,of);
        if (l==0) g_gh[o*3*HD + r] = p + gru_bh[r];
    }
}

// ======================= zero scratch (once) =======================
__global__ void zero_kernel()
{
    int i = blockIdx.x*256 + threadIdx.x;
    if (i < BB*NSLOT*HD) g_upd[i]=0.f;
    if (i < BB*NSLOT)    g_rowsum[i]=0.f;
}

// ======================= attention iteration =======================
__global__ void __launch_bounds__(256) attn_kernel(const float* __restrict__ rs_ptr,
                                                   float* __restrict__ attn_out)
{
    __shared__ float s_slots[NSLOT*HD];
    __shared__ float s_s2[NSLOT], s_sr[NSLOT];
    const int b = blockIdx.x >> 4;
    const int nbase = (blockIdx.x & 15) * 128;
    const int tid=threadIdx.x, w=tid>>5, l=tid&31;
    {
        const float4* ss=(const float4*)(g_slots + (size_t)b*NSLOT*HD);
        float4* sd=(float4*)s_slots;
        for (int i=tid;i<NSLOT*HD/4;i+=256) sd[i]=ss[i];
        if (tid<NSLOT){ s_s2[tid]=g_s2[b*NSLOT+tid]; s_sr[tid]=g_sr[b*NSLOT+tid]; }
    }
    __syncthreads();
    const float rs = *rs_ptr;
    float4 acc[NSLOT];
    #pragma unroll
    for (int k=0;k<NSLOT;k++) acc[k]=make_float4(0.f,0.f,0.f,0.f);
    float rsum=0.f;
    const int lvl = (l<NSLOT)? (l - (l/3)*3) : 0;
    const float basel = (lvl==0)?2.f:((lvl==1)?1.f:0.5f);
    const float s2k = (l<NSLOT)? s_s2[l] : 0.f;
    const float srk = (l<NSLOT)? s_sr[l] : 0.f;
    const float4* slots4=(const float4*)s_slots;

    for (int ii=0;ii<16;ii++){
        const int n = nbase + w*16 + ii;
        const size_t off = (size_t)b*NNP + n;
        float4 f = ((const float4*)(g_feats + off*HD))[l];
        float f2n = g_f2[off];
        float frn = g_fr[off];
        float dens= g_density[off];
        float mod = rs*(dens-0.5f);
        float mydot=0.f;
        #pragma unroll
        for (int k=0;k<NSLOT;k++){
            float4 sv=slots4[k*32+l];
            float p = f.x*sv.x+f.y*sv.y+f.z*sv.z+f.w*sv.w;
            p += __shfl_xor_sync(0xffffffffu,p,16);
            p += __shfl_xor_sync(0xffffffffu,p,8);
            p += __shfl_xor_sync(0xffffffffu,p,4);
            p += __shfl_xor_sync(0xffffffffu,p,2);
            p += __shfl_xor_sync(0xffffffffu,p,1);
            if (l==k) mydot=p;
        }
        float logit=-1e30f;
        if (l<NSLOT){
            float diff2 = fmaxf(f2n + s2k - 2.f*mydot, 0.f);
            float xn = fminf(f2n, 1.f-1e-5f);
            float yn = fminf(s2k, 1.f-1e-5f);
            float den = fmaxf((1.f-xn)*(1.f-yn), 1e-6f);
            float arg = fmaxf(1.f + 2.f*diff2/den, 1.f+1e-6f);
            float hd = acoshf(arg);
            float rd = fabsf(frn-srk);
            float scv = fminf(fmaxf(basel+mod,0.3f),3.f);
            logit = (-hd - 3.f*rd)*scv*10.f;   // /TAU
        }
        float m=logit;
        #pragma unroll
        for (int o=16;o;o>>=1) m=fmaxf(m,__shfl_xor_sync(0xffffffffu,m,o));
        float e=(l<NSLOT)? expf(logit-m):0.f;
        float s=e;
        #pragma unroll
        for (int o=16;o;o>>=1) s+=__shfl_xor_sync(0xffffffffu,s,o);
        float a=e/s;
        if (l<NSLOT){
            attn_out[((size_t)b*NSLOT+l)*NNP + n]=a;
            rsum += a;
        }
        #pragma unroll
        for (int k=0;k<NSLOT;k++){
            float ak=__shfl_sync(0xffffffffu,a,k);
            acc[k].x=fmaf(ak,f.x,acc[k].x); acc[k].y=fmaf(ak,f.y,acc[k].y);
            acc[k].z=fmaf(ak,f.z,acc[k].z); acc[k].w=fmaf(ak,f.w,acc[k].w);
        }
    }
    if (l<NSLOT) atomicAdd(&g_rowsum[b*NSLOT+l], rsum);
    #pragma unroll
    for (int k=0;k<NSLOT;k++){
        float* up = g_upd + ((size_t)b*NSLOT+k)*HD + l*4;
        atomicAdd(up+0,acc[k].x); atomicAdd(up+1,acc[k].y);
        atomicAdd(up+2,acc[k].z); atomicAdd(up+3,acc[k].w);
    }
}

// ======================= GRU + MLP + renorm (+ zero consumed scratch) =======================
__device__ __forceinline__ float blksum128(float v, volatile float* red){
    #pragma unroll
    for (int o=16;o;o>>=1) v += __shfl_xor_sync(0xffffffffu,v,o);
    __syncthreads();
    if ((threadIdx.x&31)==0) red[threadIdx.x>>5]=v;
    __syncthreads();
    return red[0]+red[1]+red[2]+red[3];
}

__global__ void gru_kernel(const float* __restrict__ obj_dirs,
    const float* __restrict__ gru_wi, const float* __restrict__ gru_bi,
    const float* __restrict__ mlp_w1, const float* __restrict__ mlp_b1,
    const float* __restrict__ mlp_w2, const float* __restrict__ mlp_b2,
    const float* __restrict__ norm_g, const float* __restrict__ norm_b,
    float* __restrict__ slots_out)
{
    __shared__ float s_buf[HD];
    __shared__ float s_red[4];
    const int b = blockIdx.x >> 3, o = blockIdx.x & 7;
    const int h = threadIdx.x;
    float ou=0.f;
    #pragma unroll
    for (int lv=0;lv<3;lv++){
        int k=o*3+lv;
        ou += g_upd[((size_t)b*NSLOT+k)*HD + h] / (g_rowsum[b*NSLOT+k]+1e-8f);
    }
    s_buf[h]=ou; __syncthreads();
    #pragma unroll
    for (int lv=0;lv<3;lv++){
        int k=o*3+lv;
        g_upd[((size_t)b*NSLOT+k)*HD + h]=0.f;
        if (h==lv) g_rowsum[b*NSLOT+k]=0.f;
    }
    float gi[3];
    #pragma unroll
    for (int p=0;p<3;p++){
        int r=p*HD+h;
        float a=gru_bi[r];
        const float* wr=gru_wi+(size_t)r*HD;
        #pragma unroll 8
        for (int hh=0;hh<HD;hh++) a=fmaf(s_buf[hh],wr[hh],a);
        gi[p]=a;
    }
    float hr=g_gh[o*3*HD + h], hz=g_gh[o*3*HD + HD + h], hn=g_gh[o*3*HD + 2*HD + h];
    float rr=sigmoidf(gi[0]+hr);
    float z =sigmoidf(gi[1]+hz);
    float nnv=tanhf(gi[2]+rr*hn);
    float oldh=obj_dirs[o*HD+h];
    float nd=(1.f-z)*nnv + z*oldh;
    float s = blksum128(nd, s_red);
    float q = blksum128(nd*nd, s_red);
    float mu=s*(1.f/HD), var=q*(1.f/HD)-mu*mu;
    float ln=(nd-mu)*rsqrtf(var+1e-5f)*norm_g[h]+norm_b[h];
    __syncthreads(); s_buf[h]=ln; __syncthreads();
    float m1=mlp_b1[h];
    {
        const float* w1=mlp_w1;
        #pragma unroll 8
        for (int hh=0;hh<HD;hh++) m1=fmaf(s_buf[hh],w1[(size_t)hh*HD+h],m1);
    }
    m1=geluf(m1);
    __syncthreads(); s_buf[h]=m1; __syncthreads();
    float m2=mlp_b2[h];
    {
        const float* w2=mlp_w2;
        #pragma unroll 8
        for (int hh=0;hh<HD;hh++) m2=fmaf(s_buf[hh],w2[(size_t)hh*HD+h],m2);
    }
    float nd2 = nd + 0.2f*m2;
    float q2 = blksum128(nd2*nd2, s_red);
    float nrm = fmaxf(sqrtf(q2),1e-12f);
    float ndn = nd2/nrm;
    float qn = q2/(nrm*nrm);
    const float radii[3]={0.2f,0.5f,0.8f};
    #pragma unroll
    for (int lv=0;lv<3;lv++){
        float r=radii[lv];
        float v=ndn*r;
        size_t idx=((size_t)b*NSLOT + o*3+lv)*HD + h;
        g_slots[idx]=v;
        slots_out[idx]=v;
    }
    if (h<3){
        float r=radii[h];
        float s2v=qn*r*r;
        g_s2[b*NSLOT + o*3 + h]=s2v;
        g_sr[b*NSLOT + o*3 + h]=sqrtf(s2v);
    }
}

// ======================= host launch =======================
extern "C" void kernel_launch(void* const* d_in, const int* in_sizes, int n_in,
                              void* d_out, int out_size)
{
    const float* x      = (const float*)d_in[0];
    const float* fe_w1  = (const float*)d_in[1];
    const float* fe_b1  = (const float*)d_in[2];
    const float* ln1_g  = (const float*)d_in[3];
    const float* ln1_b  = (const float*)d_in[4];
    const float* fe_w2  = (const float*)d_in[5];
    const float* fe_b2  = (const float*)d_in[6];
    const float* ln2_g  = (const float*)d_in[7];
    const float* ln2_b  = (const float*)d_in[8];
    const float* hp_w   = (const float*)d_in[9];
    const float* hp_b   = (const float*)d_in[10];
    const float* obj_dirs = (const float*)d_in[11];
    const float* radius_scale = (const float*)d_in[12];
    const float* gru_wi = (const float*)d_in[13];
    const float* gru_wh = (const float*)d_in[14];
    const float* gru_bi = (const float*)d_in[15];
    const float* gru_bh = (const float*)d_in[16];
    const float* mlp_w1 = (const float*)d_in[17];
    const float* mlp_b1 = (const float*)d_in[18];
    const float* mlp_w2 = (const float*)d_in[19];
    const float* mlp_b2 = (const float*)d_in[20];
    const float* norm_g = (const float*)d_in[21];
    const float* norm_b = (const float*)d_in[22];

    float* out = (float*)d_out;
    float* slots_out = out;                                   // [16,24,128]
    float* attn_out  = out + BB*NSLOT*HD;                     // [16,24,2048]
    float* dens_out  = attn_out + (size_t)BB*NSLOT*NNP;       // [16,2048]

    size_t encSmem = (size_t)ENC_SMEM_FLOATS*sizeof(float);   // 212,992 B
    cudaFuncSetAttribute(enc_kernel, cudaFuncAttributeMaxDynamicSharedMemorySize, (int)encSmem);

    // Order keeps the profiled launch (0-based index 3) on enc_kernel this round.
    xbf_kernel<<<BB*NNP*IND/2/256, 256>>>(x);                                          // 0
    gh_kernel<<<NOBJ, 256>>>(obj_dirs, gru_wh, gru_bh);                                // 1
    slots_init_kernel<<<1, 256>>>(obj_dirs);                                           // 2
    enc_kernel<<<BB*NNP/64, 256, encSmem>>>(x, fe_w1, fe_b1, ln1_g, ln1_b,
                                            fe_w2, fe_b2, ln2_g, ln2_b, hp_w, hp_b);   // 3 <- profiled
    {
        dim3 g(NNP/64, BB);
        dens_kernel<<<g, 256>>>(dens_out);                                             // 4
    }
    feats_kernel<<<BB*NNP/8, 256>>>();                                                 // 5
    zero_kernel<<<(BB*NSLOT*HD+255)/256, 256>>>();                                     // 6

    for (int it=0; it<NITER; it++){
        attn_kernel<<<BB*16, 256>>>(radius_scale, attn_out);
        gru_kernel<<<BB*NOBJ, 128>>>(obj_dirs, gru_wi, gru_bi,
                                     mlp_w1, mlp_b1, mlp_w2, mlp_b2,
                                     norm_g, norm_b, slots_out);
    }
}

// round 10
// speedup vs baseline: 1.1444x; 1.1444x over previous
#include <cuda_runtime.h>
#include <cuda_bf16.h>
#include <math.h>

#define BB 16
#define NNP 2048
#define IND 64
#define HD 128
#define NOBJ 8
#define NSLOT 24
#define NITER 3

// ---------------- device scratch (static, no allocation) ----------------
__device__ float g_hyp[BB*NNP*HD];
__device__ float g_feats[BB*NNP*HD];
__device__ float g_x2[BB*NNP];
__device__ float g_f2[BB*NNP];
__device__ float g_fr[BB*NNP];
__device__ float g_density[BB*NNP];
__device__ float g_slots[BB*NSLOT*HD];
__device__ float g_s2[BB*NSLOT];
__device__ float g_sr[BB*NSLOT];
__device__ float g_gh[NOBJ*3*HD];
__device__ float g_upd[BB*NSLOT*HD];
__device__ float g_rowsum[BB*NSLOT];
__device__ __nv_bfloat162 g_xbf2[BB*NNP*IND/2];

__device__ __forceinline__ float geluf(float x){
    return 0.5f*x*(1.f+erff(x*0.70710678118654752f));
}
__device__ __forceinline__ float sigmoidf(float x){
    return 1.f/(1.f+expf(-x));
}

// ======================= encoder (resident weights) =======================
#define ENC_SMEM_FLOATS (IND*HD + HD*HD + HD*HD + 64*IND + 64*HD)   // 212,992 B

__global__ void __launch_bounds__(256) enc_kernel(const float* __restrict__ x,
    const float* __restrict__ fe_w1, const float* __restrict__ fe_b1,
    const float* __restrict__ ln1_g, const float* __restrict__ ln1_b,
    const float* __restrict__ fe_w2, const float* __restrict__ fe_b2,
    const float* __restrict__ ln2_g, const float* __restrict__ ln2_b,
    const float* __restrict__ hp_w,  const float* __restrict__ hp_b)
{
    extern __shared__ float sm[];
    float* s_w1 = sm;
    float* s_w2 = s_w1 + IND*HD;
    float* s_w3 = s_w2 + HD*HD;
    float* s_x  = s_w3 + HD*HD;
    float* s_h  = s_x  + 64*IND;

    const int tid = threadIdx.x;
    const int tokbase = blockIdx.x*64;
    {
        const float4* a=(const float4*)fe_w1; float4* d1=(float4*)s_w1;
        for (int i=tid;i<IND*HD/4;i+=256) d1[i]=a[i];
        const float4* b=(const float4*)fe_w2; float4* d2=(float4*)s_w2;
        for (int i=tid;i<HD*HD/4;i+=256) d2[i]=b[i];
        const float4* c=(const float4*)hp_w; float4* d3=(float4*)s_w3;
        for (int i=tid;i<HD*HD/4;i+=256) d3[i]=c[i];
        const float4* xs=(const float4*)(x + (size_t)tokbase*IND); float4* xd=(float4*)s_x;
        for (int i=tid;i<64*IND/4;i+=256) xd[i]=xs[i];
    }
    __syncthreads();
    if (tid < 64){
        float s=0.f;
        #pragma unroll 8
        for (int k=0;k<IND;k++){ float v=s_x[tid*IND+k]; s+=v*v; }
        g_x2[tokbase+tid]=s;
    }
    const int w = tid>>5, l = tid&31;

    float acc[8][4];
    #pragma unroll
    for (int t=0;t<8;t++){acc[t][0]=acc[t][1]=acc[t][2]=acc[t][3]=0.f;}
    {
        const float4* w4=(const float4*)s_w1;
        for (int k=0;k<IND;k++){
            float4 wv = w4[k*32+l];
            #pragma unroll
            for (int t=0;t<8;t++){
                float xv = s_x[(w*8+t)*IND + k];
                acc[t][0]=fmaf(xv,wv.x,acc[t][0]); acc[t][1]=fmaf(xv,wv.y,acc[t][1]);
                acc[t][2]=fmaf(xv,wv.z,acc[t][2]); acc[t][3]=fmaf(xv,wv.w,acc[t][3]);
            }
        }
    }
    {
        float4 bv=((const float4*)fe_b1)[l];
        float4 gv=((const float4*)ln1_g)[l];
        float4 bt=((const float4*)ln1_b)[l];
        #pragma unroll
        for (int t=0;t<8;t++){
            float v0=acc[t][0]+bv.x, v1=acc[t][1]+bv.y, v2=acc[t][2]+bv.z, v3=acc[t][3]+bv.w;
            float s=v0+v1+v2+v3, q=v0*v0+v1*v1+v2*v2+v3*v3;
            #pragma unroll
            for (int o=16;o;o>>=1){ s+=__shfl_xor_sync(0xffffffffu,s,o); q+=__shfl_xor_sync(0xffffffffu,q,o); }
            float mu=s*(1.f/HD), var=q*(1.f/HD)-mu*mu;
            float inv=rsqrtf(var+1e-5f);
            v0=geluf((v0-mu)*inv*gv.x+bt.x); v1=geluf((v1-mu)*inv*gv.y+bt.y);
            v2=geluf((v2-mu)*inv*gv.z+bt.z); v3=geluf((v3-mu)*inv*gv.w+bt.w);
            float4* hv=(float4*)&s_h[(w*8+t)*HD + l*4];
            *hv = make_float4(v0,v1,v2,v3);
        }
    }
    __syncwarp();
    #pragma unroll
    for (int t=0;t<8;t++){acc[t][0]=acc[t][1]=acc[t][2]=acc[t][3]=0.f;}
    {
        const float4* w4=(const float4*)s_w2;
        for (int k=0;k<HD;k++){
            float4 wv = w4[k*32+l];
            #pragma unroll
            for (int t=0;t<8;t++){
                float xv = s_h[(w*8+t)*HD + k];
                acc[t][0]=fmaf(xv,wv.x,acc[t][0]); acc[t][1]=fmaf(xv,wv.y,acc[t][1]);
                acc[t][2]=fmaf(xv,wv.z,acc[t][2]); acc[t][3]=fmaf(xv,wv.w,acc[t][3]);
            }
        }
    }
    {
        float4 bv=((const float4*)fe_b2)[l];
        float4 gv=((const float4*)ln2_g)[l];
        float4 bt=((const float4*)ln2_b)[l];
        #pragma unroll
        for (int t=0;t<8;t++){
            float v0=acc[t][0]+bv.x, v1=acc[t][1]+bv.y, v2=acc[t][2]+bv.z, v3=acc[t][3]+bv.w;
            float s=v0+v1+v2+v3, q=v0*v0+v1*v1+v2*v2+v3*v3;
            #pragma unroll
            for (int o=16;o;o>>=1){ s+=__shfl_xor_sync(0xffffffffu,s,o); q+=__shfl_xor_sync(0xffffffffu,q,o); }
            float mu=s*(1.f/HD), var=q*(1.f/HD)-mu*mu;
            float inv=rsqrtf(var+1e-5f);
            acc[t][0]=(v0-mu)*inv*gv.x+bt.x; acc[t][1]=(v1-mu)*inv*gv.y+bt.y;
            acc[t][2]=(v2-mu)*inv*gv.z+bt.z; acc[t][3]=(v3-mu)*inv*gv.w+bt.w;
        }
    }
    __syncwarp();
    #pragma unroll
    for (int t=0;t<8;t++){
        float4* hv=(float4*)&s_h[(w*8+t)*HD + l*4];
        *hv = make_float4(acc[t][0],acc[t][1],acc[t][2],acc[t][3]);
    }
    __syncwarp();
    #pragma unroll
    for (int t=0;t<8;t++){acc[t][0]=acc[t][1]=acc[t][2]=acc[t][3]=0.f;}
    {
        const float4* w4=(const float4*)s_w3;
        for (int k=0;k<HD;k++){
            float4 wv = w4[k*32+l];
            #pragma unroll
            for (int t=0;t<8;t++){
                float xv = s_h[(w*8+t)*HD + k];
                acc[t][0]=fmaf(xv,wv.x,acc[t][0]); acc[t][1]=fmaf(xv,wv.y,acc[t][1]);
                acc[t][2]=fmaf(xv,wv.z,acc[t][2]); acc[t][3]=fmaf(xv,wv.w,acc[t][3]);
            }
        }
    }
    {
        float4 bv=((const float4*)hp_b)[l];
        #pragma unroll
        for (int t=0;t<8;t++){
            float4 hv;
            hv.x=tanhf(acc[t][0]+bv.x); hv.y=tanhf(acc[t][1]+bv.y);
            hv.z=tanhf(acc[t][2]+bv.z); hv.w=tanhf(acc[t][3]+bv.w);
            ((float4*)(g_hyp + (size_t)(tokbase + w*8 + t)*HD))[l]=hv;
        }
    }
}

// ======================= prep: xbf + zero scratch + slots init (merged) =======================
__global__ void prep_kernel(const float* __restrict__ x, const float* __restrict__ obj_dirs)
{
    const int bid = blockIdx.x, tid = threadIdx.x;
    int i = bid*256 + tid;
    float2 v = ((const float2*)x)[i];
    g_xbf2[i] = __float22bfloat162_rn(v);

    if (bid < 192){
        g_upd[bid*256 + tid] = 0.f;
    } else if (bid == 192){
        if (tid < BB*NSLOT) g_rowsum[tid] = 0.f;
    } else if (bid == 193){
        const int w=tid>>5, l=tid&31;
        if (w<NOBJ){
            float4 od=((const float4*)(obj_dirs + w*HD))[l];
            float q=od.x*od.x+od.y*od.y+od.z*od.z+od.w*od.w;
            #pragma unroll
            for (int o=16;o;o>>=1) q += __shfl_xor_sync(0xffffffffu,q,o);
            float nrm=sqrtf(q);
            float inv=1.f/fmaxf(nrm,1e-12f);
            float4 dn=make_float4(od.x*inv,od.y*inv,od.z*inv,od.w*inv);
            float qn=q*inv*inv;
            const float radii[3]={0.2f,0.5f,0.8f};
            for (int b=0;b<BB;b++){
                #pragma unroll
                for (int lv=0;lv<3;lv++){
                    float r=radii[lv];
                    ((float4*)(g_slots + (size_t)(b*NSLOT + w*3+lv)*HD))[l] =
                        make_float4(dn.x*r,dn.y*r,dn.z*r,dn.w*r);
                    if (l==0){
                        float s2=qn*r*r;
                        g_s2[b*NSLOT + w*3+lv]=s2;
                        g_sr[b*NSLOT + w*3+lv]=sqrtf(s2);
                    }
                }
            }
        }
    }
}

// ======================= density + feats (merged) =======================
__device__ __forceinline__ void ins6(float t[6], float v){
    if (v < t[5]){
        t[5]=v;
        #pragma unroll
        for (int s=5;s>0;s--){ if (t[s]<t[s-1]){ float tmp=t[s-1]; t[s-1]=t[s]; t[s]=tmp; } }
    }
}

#define JT_STRIDE 72

__global__ void __launch_bounds__(256) densfeats_kernel(float* __restrict__ dens_out)
{
    __shared__ float smf[3200];
    __nv_bfloat16* sxj = (__nv_bfloat16*)smf;
    float* x2s  = smf + (64*JT_STRIDE*2)/4;
    float* cand = smf;                         // [64][49] = 3136 floats
    float* s_dens = smf + 3136;                // [64]

    const int b  = blockIdx.y;
    const int i0 = blockIdx.x * 64;
    const int tid = threadIdx.x, w = tid>>5, lane = tid&31;
    const int g = lane>>2, tg = lane&3;
    const int rg = w & 3;
    const int jh = w >> 2;
    const int r0 = i0 + rg*16 + g;
    const unsigned short* xb = (const unsigned short*)g_xbf2 + (size_t)b*NNP*IND;

    unsigned int A[4][4];
    {
        const unsigned short* xr0 = xb + (size_t)r0*IND;
        const unsigned short* xr1 = xr0 + 8*IND;
        #pragma unroll
        for (int ks=0;ks<4;ks++){
            int kb = ks*16 + tg*2;
            A[ks][0] = *(const unsigned int*)&xr0[kb];
            A[ks][1] = *(const unsigned int*)&xr1[kb];
            A[ks][2] = *(const unsigned int*)&xr0[kb+8];
            A[ks][3] = *(const unsigned int*)&xr1[kb+8];
        }
    }
    float t6[2][6];
    #pragma unroll
    for (int r=0;r<2;r++){
        #pragma unroll
        for (int s=0;s<6;s++) t6[r][s]=1e30f;
    }

    for (int jt=0; jt<32; jt++){
        __syncthreads();
        {
            #pragma unroll
            for (int p=0;p<8;p++){
                int idx = tid + 256*p;
                int row = idx >> 5, c = idx & 31;
                unsigned int v = *(const unsigned int*)&xb[((size_t)(jt*64 + row))*IND + c*2];
                *(unsigned int*)&sxj[row*JT_STRIDE + c*2] = v;
            }
            if (tid < 64) x2s[tid] = g_x2[b*NNP + jt*64 + tid];
        }
        __syncthreads();
        #pragma unroll
        for (int q=0;q<4;q++){
            const int nt = jh*4 + q;
            const int n  = nt*8 + g;
            float c0=0.f,c1=0.f,c2=0.f,c3=0.f;
            #pragma unroll
            for (int ks=0;ks<4;ks++){
                const __nv_bfloat16* bp = &sxj[n*JT_STRIDE + ks*16 + tg*2];
                unsigned int B0 = *(const unsigned int*)bp;
                unsigned int B1 = *(const unsigned int*)(bp+8);
                asm("mma.sync.aligned.m16n8k16.row.col.f32.bf16.bf16.f32 "
                    "{%0,%1,%2,%3}, {%4,%5,%6,%7}, {%8,%9}, {%0,%1,%2,%3};"
                    : "+f"(c0),"+f"(c1),"+f"(c2),"+f"(c3)
                    : "r"(A[ks][0]),"r"(A[ks][1]),"r"(A[ks][2]),"r"(A[ks][3]),
                      "r"(B0),"r"(B1));
            }
            const int lc = nt*8 + tg*2;
            float xa = x2s[lc], xc = x2s[lc+1];
            ins6(t6[0], xa - 2.f*c0); ins6(t6[0], xc - 2.f*c1);
            ins6(t6[1], xa - 2.f*c2); ins6(t6[1], xc - 2.f*c3);
        }
    }
    __syncthreads();
    {
        int lr0 = rg*16 + g;
        int base = jh*24 + tg*6;
        #pragma unroll
        for (int s=0;s<6;s++){
            cand[lr0*49 + base + s]     = t6[0][s];
            cand[(lr0+8)*49 + base + s] = t6[1][s];
        }
    }
    __syncthreads();
    if (tid < 64){
        float u[6]={1e30f,1e30f,1e30f,1e30f,1e30f,1e30f};
        const float* row = &cand[tid*49];
        #pragma unroll 8
        for (int m=0;m<48;m++) ins6(u, row[m]);
        float x2i = g_x2[b*NNP + i0 + tid];
        float md = (sqrtf(fmaxf(x2i+u[1],0.f)) + sqrtf(fmaxf(x2i+u[2],0.f))
                  + sqrtf(fmaxf(x2i+u[3],0.f)) + sqrtf(fmaxf(x2i+u[4],0.f))
                  + sqrtf(fmaxf(x2i+u[5],0.f))) * 0.2f;
        float dv = tanhf(md);
        s_dens[tid] = dv;
        g_density[b*NNP + i0 + tid] = dv;
        dens_out [b*NNP + i0 + tid] = dv;
    }
    __syncthreads();
    // ---- feats phase: this block owns rows i0..i0+63 ----
    #pragma unroll
    for (int t=0;t<8;t++){
        int row = w*8 + t;
        size_t n = (size_t)b*NNP + i0 + row;
        float4 v = ((const float4*)(g_hyp + n*HD))[lane];
        float q = v.x*v.x+v.y*v.y+v.z*v.z+v.w*v.w;
        #pragma unroll
        for (int o=16;o;o>>=1) q += __shfl_xor_sync(0xffffffffu,q,o);
        float fn = fmaxf(sqrtf(q),1e-6f);
        float dens = s_dens[row];
        float tr = (0.3f+0.5f*(1.f-dens))*0.95f;
        float sc = tr/fn;
        ((float4*)(g_feats + n*HD))[lane] = make_float4(v.x*sc,v.y*sc,v.z*sc,v.w*sc);
        if (lane==0){
            float f2=q*sc*sc;
            g_f2[n]=f2; g_fr[n]=sqrtf(f2);
        }
    }
}

// ======================= gh precompute =======================
__global__ void gh_kernel(const float* __restrict__ obj_dirs,
                          const float* __restrict__ gru_wh,
                          const float* __restrict__ gru_bh)
{
    const int o = blockIdx.x;
    const int w = threadIdx.x>>5, l = threadIdx.x&31;
    float4 od = ((const float4*)(obj_dirs + (size_t)o*HD))[l];
    for (int m=0;m<48;m++){
        int r = w*48 + m;
        float4 wv = ((const float4*)(gru_wh + (size_t)r*HD))[l];
        float p = od.x*wv.x + od.y*wv.y + od.z*wv.z + od.w*wv.w;
        #pragma unroll
        for (int of=16;of;of>>=1) p += __shfl_xor_sync(0xffffffffu,p,of);
        if (l==0) g_gh[o*3*HD + r] = p + gru_bh[r];
    }
}

// ======================= attention iteration (smem-reduced update accumulation) =======================
__global__ void __launch_bounds__(256) attn_kernel(const float* __restrict__ rs_ptr,
                                                   float* __restrict__ attn_out)
{
    __shared__ float s_slots[NSLOT*HD];
    __shared__ float s_upd[NSLOT*HD];
    __shared__ float s_s2[NSLOT], s_sr[NSLOT], s_rs[NSLOT];
    const int b = blockIdx.x >> 4;
    const int nbase = (blockIdx.x & 15) * 128;
    const int tid=threadIdx.x, w=tid>>5, l=tid&31;
    {
        const float4* ss=(const float4*)(g_slots + (size_t)b*NSLOT*HD);
        float4* sd=(float4*)s_slots;
        float4* zu=(float4*)s_upd;
        for (int i=tid;i<NSLOT*HD/4;i+=256){ sd[i]=ss[i]; zu[i]=make_float4(0.f,0.f,0.f,0.f); }
        if (tid<NSLOT){ s_s2[tid]=g_s2[b*NSLOT+tid]; s_sr[tid]=g_sr[b*NSLOT+tid]; s_rs[tid]=0.f; }
    }
    __syncthreads();
    const float rs = *rs_ptr;
    float4 acc[NSLOT];
    #pragma unroll
    for (int k=0;k<NSLOT;k++) acc[k]=make_float4(0.f,0.f,0.f,0.f);
    float rsum=0.f;
    const int lvl = (l<NSLOT)? (l - (l/3)*3) : 0;
    const float basel = (lvl==0)?2.f:((lvl==1)?1.f:0.5f);
    const float s2k = (l<NSLOT)? s_s2[l] : 0.f;
    const float srk = (l<NSLOT)? s_sr[l] : 0.f;
    const float4* slots4=(const float4*)s_slots;

    for (int ii=0;ii<16;ii++){
        const int n = nbase + w*16 + ii;
        const size_t off = (size_t)b*NNP + n;
        float4 f = ((const float4*)(g_feats + off*HD))[l];
        float f2n = g_f2[off];
        float frn = g_fr[off];
        float dens= g_density[off];
        float mod = rs*(dens-0.5f);
        float mydot=0.f;
        #pragma unroll
        for (int k=0;k<NSLOT;k++){
            float4 sv=slots4[k*32+l];
            float p = f.x*sv.x+f.y*sv.y+f.z*sv.z+f.w*sv.w;
            p += __shfl_xor_sync(0xffffffffu,p,16);
            p += __shfl_xor_sync(0xffffffffu,p,8);
            p += __shfl_xor_sync(0xffffffffu,p,4);
            p += __shfl_xor_sync(0xffffffffu,p,2);
            p += __shfl_xor_sync(0xffffffffu,p,1);
            if (l==k) mydot=p;
        }
        float logit=-1e30f;
        if (l<NSLOT){
            float diff2 = fmaxf(f2n + s2k - 2.f*mydot, 0.f);
            float xn = fminf(f2n, 1.f-1e-5f);
            float yn = fminf(s2k, 1.f-1e-5f);
            float den = fmaxf((1.f-xn)*(1.f-yn), 1e-6f);
            float arg = fmaxf(1.f + 2.f*diff2/den, 1.f+1e-6f);
            float hd = acoshf(arg);
            float rd = fabsf(frn-srk);
            float scv = fminf(fmaxf(basel+mod,0.3f),3.f);
            logit = (-hd - 3.f*rd)*scv*10.f;   // /TAU
        }
        float m=logit;
        #pragma unroll
        for (int o=16;o;o>>=1) m=fmaxf(m,__shfl_xor_sync(0xffffffffu,m,o));
        float e=(l<NSLOT)? expf(logit-m):0.f;
        float s=e;
        #pragma unroll
        for (int o=16;o;o>>=1) s+=__shfl_xor_sync(0xffffffffu,s,o);
        float a=e/s;
        if (l<NSLOT){
            attn_out[((size_t)b*NSLOT+l)*NNP + n]=a;
            rsum += a;
        }
        #pragma unroll
        for (int k=0;k<NSLOT;k++){
            float ak=__shfl_sync(0xffffffffu,a,k);
            acc[k].x=fmaf(ak,f.x,acc[k].x); acc[k].y=fmaf(ak,f.y,acc[k].y);
            acc[k].z=fmaf(ak,f.z,acc[k].z); acc[k].w=fmaf(ak,f.w,acc[k].w);
        }
    }
    // block-level smem reduction, then few coalesced global atomics
    if (l<NSLOT) atomicAdd(&s_rs[l], rsum);
    #pragma unroll
    for (int k=0;k<NSLOT;k++){
        float* up = s_upd + k*HD + l*4;
        atomicAdd(up+0,acc[k].x); atomicAdd(up+1,acc[k].y);
        atomicAdd(up+2,acc[k].z); atomicAdd(up+3,acc[k].w);
    }
    __syncthreads();
    for (int idx=tid; idx<NSLOT*HD; idx+=256)
        atomicAdd(&g_upd[(size_t)b*NSLOT*HD + idx], s_upd[idx]);
    if (tid<NSLOT) atomicAdd(&g_rowsum[b*NSLOT+tid], s_rs[tid]);
}

// ======================= GRU + MLP + renorm (warp-row gi, coalesced) =======================
__device__ __forceinline__ float blksum128(float v, volatile float* red){
    #pragma unroll
    for (int o=16;o;o>>=1) v += __shfl_xor_sync(0xffffffffu,v,o);
    __syncthreads();
    if ((threadIdx.x&31)==0) red[threadIdx.x>>5]=v;
    __syncthreads();
    return red[0]+red[1]+red[2]+red[3];
}

__global__ void __launch_bounds__(128) gru_kernel(const float* __restrict__ obj_dirs,
    const float* __restrict__ gru_wi, const float* __restrict__ gru_bi,
    const float* __restrict__ mlp_w1, const float* __restrict__ mlp_b1,
    const float* __restrict__ mlp_w2, const float* __restrict__ mlp_b2,
    const float* __restrict__ norm_g, const float* __restrict__ norm_b,
    float* __restrict__ slots_out)
{
    __shared__ float s_buf[HD];
    __shared__ float s_gi[3*HD];
    __shared__ float s_red[4];
    const int b = blockIdx.x >> 3, o = blockIdx.x & 7;
    const int h = threadIdx.x, w = h>>5, l = h&31;
    float ou=0.f;
    #pragma unroll
    for (int lv=0;lv<3;lv++){
        int k=o*3+lv;
        ou += g_upd[((size_t)b*NSLOT+k)*HD + h] / (g_rowsum[b*NSLOT+k]+1e-8f);
    }
    s_buf[h]=ou; __syncthreads();
    // zero the scratch this block exclusively owns (for next attn iteration)
    #pragma unroll
    for (int lv=0;lv<3;lv++){
        int k=o*3+lv;
        g_upd[((size_t)b*NSLOT+k)*HD + h]=0.f;
        if (h==lv) g_rowsum[b*NSLOT+k]=0.f;
    }
    // gi: warp-per-row dots with COALESCED weight row reads
    {
        float4 ob = ((const float4*)s_buf)[l];
        for (int m=0;m<96;m++){
            int r = w*96 + m;
            float4 wv = ((const float4*)(gru_wi + (size_t)r*HD))[l];
            float p = ob.x*wv.x + ob.y*wv.y + ob.z*wv.z + ob.w*wv.w;
            #pragma unroll
            for (int of=16;of;of>>=1) p += __shfl_xor_sync(0xffffffffu,p,of);
            if (l==0) s_gi[r] = p + gru_bi[r];
        }
    }
    __syncthreads();
    float hr=g_gh[o*3*HD + h], hz=g_gh[o*3*HD + HD + h], hn=g_gh[o*3*HD + 2*HD + h];
    float rr=sigmoidf(s_gi[h]+hr);
    float z =sigmoidf(s_gi[HD+h]+hz);
    float nnv=tanhf(s_gi[2*HD+h]+rr*hn);
    float oldh=obj_dirs[o*HD+h];
    float nd=(1.f-z)*nnv + z*oldh;
    float s = blksum128(nd, s_red);
    float q = blksum128(nd*nd, s_red);
    float mu=s*(1.f/HD), var=q*(1.f/HD)-mu*mu;
    float ln=(nd-mu)*rsqrtf(var+1e-5f)*norm_g[h]+norm_b[h];
    __syncthreads(); s_buf[h]=ln; __syncthreads();
    float m1=mlp_b1[h];
    {
        const float* w1=mlp_w1;
        #pragma unroll 8
        for (int hh=0;hh<HD;hh++) m1=fmaf(s_buf[hh],w1[(size_t)hh*HD+h],m1);   // coalesced
    }
    m1=geluf(m1);
    __syncthreads(); s_buf[h]=m1; __syncthreads();
    float m2=mlp_b2[h];
    {
        const float* w2=mlp_w2;
        #pragma unroll 8
        for (int hh=0;hh<HD;hh++) m2=fmaf(s_buf[hh],w2[(size_t)hh*HD+h],m2);   // coalesced
    }
    float nd2 = nd + 0.2f*m2;
    float q2 = blksum128(nd2*nd2, s_red);
    float nrm = fmaxf(sqrtf(q2),1e-12f);
    float ndn = nd2/nrm;
    float qn = q2/(nrm*nrm);
    const float radii[3]={0.2f,0.5f,0.8f};
    #pragma unroll
    for (int lv=0;lv<3;lv++){
        float r=radii[lv];
        float v=ndn*r;
        size_t idx=((size_t)b*NSLOT + o*3+lv)*HD + h;
        g_slots[idx]=v;
        slots_out[idx]=v;
    }
    if (h<3){
        float r=radii[h];
        float s2v=qn*r*r;
        g_s2[b*NSLOT + o*3 + h]=s2v;
        g_sr[b*NSLOT + o*3 + h]=sqrtf(s2v);
    }
}

// ======================= host launch =======================
extern "C" void kernel_launch(void* const* d_in, const int* in_sizes, int n_in,
                              void* d_out, int out_size)
{
    const float* x      = (const float*)d_in[0];
    const float* fe_w1  = (const float*)d_in[1];
    const float* fe_b1  = (const float*)d_in[2];
    const float* ln1_g  = (const float*)d_in[3];
    const float* ln1_b  = (const float*)d_in[4];
    const float* fe_w2  = (const float*)d_in[5];
    const float* fe_b2  = (const float*)d_in[6];
    const float* ln2_g  = (const float*)d_in[7];
    const float* ln2_b  = (const float*)d_in[8];
    const float* hp_w   = (const float*)d_in[9];
    const float* hp_b   = (const float*)d_in[10];
    const float* obj_dirs = (const float*)d_in[11];
    const float* radius_scale = (const float*)d_in[12];
    const float* gru_wi = (const float*)d_in[13];
    const float* gru_wh = (const float*)d_in[14];
    const float* gru_bi = (const float*)d_in[15];
    const float* gru_bh = (const float*)d_in[16];
    const float* mlp_w1 = (const float*)d_in[17];
    const float* mlp_b1 = (const float*)d_in[18];
    const float* mlp_w2 = (const float*)d_in[19];
    const float* mlp_b2 = (const float*)d_in[20];
    const float* norm_g = (const float*)d_in[21];
    const float* norm_b = (const float*)d_in[22];

    float* out = (float*)d_out;
    float* slots_out = out;                                   // [16,24,128]
    float* attn_out  = out + BB*NSLOT*HD;                     // [16,24,2048]
    float* dens_out  = attn_out + (size_t)BB*NSLOT*NNP;       // [16,2048]

    size_t encSmem = (size_t)ENC_SMEM_FLOATS*sizeof(float);   // 212,992 B
    cudaFuncSetAttribute(enc_kernel, cudaFuncAttributeMaxDynamicSharedMemorySize, (int)encSmem);

    // Launch order: attn_kernel is the 0-based 4th launch (ncu capture point).
    enc_kernel<<<BB*NNP/64, 256, encSmem>>>(x, fe_w1, fe_b1, ln1_g, ln1_b,
                                            fe_w2, fe_b2, ln2_g, ln2_b, hp_w, hp_b);   // 0
    prep_kernel<<<BB*NNP*IND/2/256, 256>>>(x, obj_dirs);                               // 1
    {
        dim3 g(NNP/64, BB);
        densfeats_kernel<<<g, 256>>>(dens_out);                                        // 2
    }
    attn_kernel<<<BB*16, 256>>>(radius_scale, attn_out);                               // 3 <- profiled
    gh_kernel<<<NOBJ, 256>>>(obj_dirs, gru_wh, gru_bh);                                // 4
    gru_kernel<<<BB*NOBJ, 128>>>(obj_dirs, gru_wi, gru_bi,
                                 mlp_w1, mlp_b1, mlp_w2, mlp_b2,
                                 norm_g, norm_b, slots_out);                           // 5
    for (int it=1; it<NITER; it++){
        attn_kernel<<<BB*16, 256>>>(radius_scale, attn_out);
        gru_kernel<<<BB*NOBJ, 128>>>(obj_dirs, gru_wi, gru_bi,
                                     mlp_w1, mlp_b1, mlp_w2, mlp_b2,
                                     norm_g, norm_b, slots_out);
    }
}

// round 12
// speedup vs baseline: 1.1577x; 1.0116x over previous
#include <cuda_runtime.h>
#include <cuda_bf16.h>
#include <math.h>

#define BB 16
#define NNP 2048
#define IND 64
#define HD 128
#define NOBJ 8
#define NSLOT 24
#define NITER 3

// ---------------- device scratch (static, no allocation) ----------------
__device__ float g_hyp[BB*NNP*HD];
__device__ float g_feats[BB*NNP*HD];
__device__ float g_x2[BB*NNP];
__device__ float g_f2[BB*NNP];
__device__ float g_fr[BB*NNP];
__device__ float g_density[BB*NNP];
__device__ float g_slots[BB*NSLOT*HD];
__device__ float g_s2[BB*NSLOT];
__device__ float g_sr[BB*NSLOT];
__device__ float g_gh[NOBJ*3*HD];
__device__ float g_upd[BB*NSLOT*HD];
__device__ float g_rowsum[BB*NSLOT];
__device__ __nv_bfloat162 g_xbf2[BB*NNP*IND/2];

__device__ __forceinline__ float geluf(float x){
    return 0.5f*x*(1.f+erff(x*0.70710678118654752f));
}
__device__ __forceinline__ float sigmoidf(float x){
    return 1.f/(1.f+expf(-x));
}

// ======================= encoder (resident weights) =======================
#define ENC_SMEM_FLOATS (IND*HD + HD*HD + HD*HD + 64*IND + 64*HD)   // 212,992 B

__global__ void __launch_bounds__(256) enc_kernel(const float* __restrict__ x,
    const float* __restrict__ fe_w1, const float* __restrict__ fe_b1,
    const float* __restrict__ ln1_g, const float* __restrict__ ln1_b,
    const float* __restrict__ fe_w2, const float* __restrict__ fe_b2,
    const float* __restrict__ ln2_g, const float* __restrict__ ln2_b,
    const float* __restrict__ hp_w,  const float* __restrict__ hp_b)
{
    extern __shared__ float sm[];
    float* s_w1 = sm;
    float* s_w2 = s_w1 + IND*HD;
    float* s_w3 = s_w2 + HD*HD;
    float* s_x  = s_w3 + HD*HD;
    float* s_h  = s_x  + 64*IND;

    const int tid = threadIdx.x;
    const int tokbase = blockIdx.x*64;
    {
        const float4* a=(const float4*)fe_w1; float4* d1=(float4*)s_w1;
        for (int i=tid;i<IND*HD/4;i+=256) d1[i]=a[i];
        const float4* b=(const float4*)fe_w2; float4* d2=(float4*)s_w2;
        for (int i=tid;i<HD*HD/4;i+=256) d2[i]=b[i];
        const float4* c=(const float4*)hp_w; float4* d3=(float4*)s_w3;
        for (int i=tid;i<HD*HD/4;i+=256) d3[i]=c[i];
        const float4* xs=(const float4*)(x + (size_t)tokbase*IND); float4* xd=(float4*)s_x;
        for (int i=tid;i<64*IND/4;i+=256) xd[i]=xs[i];
    }
    __syncthreads();
    if (tid < 64){
        float s=0.f;
        #pragma unroll 8
        for (int k=0;k<IND;k++){ float v=s_x[tid*IND+k]; s+=v*v; }
        g_x2[tokbase+tid]=s;
    }
    const int w = tid>>5, l = tid&31;

    float acc[8][4];
    #pragma unroll
    for (int t=0;t<8;t++){acc[t][0]=acc[t][1]=acc[t][2]=acc[t][3]=0.f;}
    {
        const float4* w4=(const float4*)s_w1;
        for (int k=0;k<IND;k++){
            float4 wv = w4[k*32+l];
            #pragma unroll
            for (int t=0;t<8;t++){
                float xv = s_x[(w*8+t)*IND + k];
                acc[t][0]=fmaf(xv,wv.x,acc[t][0]); acc[t][1]=fmaf(xv,wv.y,acc[t][1]);
                acc[t][2]=fmaf(xv,wv.z,acc[t][2]); acc[t][3]=fmaf(xv,wv.w,acc[t][3]);
            }
        }
    }
    {
        float4 bv=((const float4*)fe_b1)[l];
        float4 gv=((const float4*)ln1_g)[l];
        float4 bt=((const float4*)ln1_b)[l];
        #pragma unroll
        for (int t=0;t<8;t++){
            float v0=acc[t][0]+bv.x, v1=acc[t][1]+bv.y, v2=acc[t][2]+bv.z, v3=acc[t][3]+bv.w;
            float s=v0+v1+v2+v3, q=v0*v0+v1*v1+v2*v2+v3*v3;
            #pragma unroll
            for (int o=16;o;o>>=1){ s+=__shfl_xor_sync(0xffffffffu,s,o); q+=__shfl_xor_sync(0xffffffffu,q,o); }
            float mu=s*(1.f/HD), var=q*(1.f/HD)-mu*mu;
            float inv=rsqrtf(var+1e-5f);
            v0=geluf((v0-mu)*inv*gv.x+bt.x); v1=geluf((v1-mu)*inv*gv.y+bt.y);
            v2=geluf((v2-mu)*inv*gv.z+bt.z); v3=geluf((v3-mu)*inv*gv.w+bt.w);
            float4* hv=(float4*)&s_h[(w*8+t)*HD + l*4];
            *hv = make_float4(v0,v1,v2,v3);
        }
    }
    __syncwarp();
    #pragma unroll
    for (int t=0;t<8;t++){acc[t][0]=acc[t][1]=acc[t][2]=acc[t][3]=0.f;}
    {
        const float4* w4=(const float4*)s_w2;
        for (int k=0;k<HD;k++){
            float4 wv = w4[k*32+l];
            #pragma unroll
            for (int t=0;t<8;t++){
                float xv = s_h[(w*8+t)*HD + k];
                acc[t][0]=fmaf(xv,wv.x,acc[t][0]); acc[t][1]=fmaf(xv,wv.y,acc[t][1]);
                acc[t][2]=fmaf(xv,wv.z,acc[t][2]); acc[t][3]=fmaf(xv,wv.w,acc[t][3]);
            }
        }
    }
    {
        float4 bv=((const float4*)fe_b2)[l];
        float4 gv=((const float4*)ln2_g)[l];
        float4 bt=((const float4*)ln2_b)[l];
        #pragma unroll
        for (int t=0;t<8;t++){
            float v0=acc[t][0]+bv.x, v1=acc[t][1]+bv.y, v2=acc[t][2]+bv.z, v3=acc[t][3]+bv.w;
            float s=v0+v1+v2+v3, q=v0*v0+v1*v1+v2*v2+v3*v3;
            #pragma unroll
            for (int o=16;o;o>>=1){ s+=__shfl_xor_sync(0xffffffffu,s,o); q+=__shfl_xor_sync(0xffffffffu,q,o); }
            float mu=s*(1.f/HD), var=q*(1.f/HD)-mu*mu;
            float inv=rsqrtf(var+1e-5f);
            acc[t][0]=(v0-mu)*inv*gv.x+bt.x; acc[t][1]=(v1-mu)*inv*gv.y+bt.y;
            acc[t][2]=(v2-mu)*inv*gv.z+bt.z; acc[t][3]=(v3-mu)*inv*gv.w+bt.w;
        }
    }
    __syncwarp();
    #pragma unroll
    for (int t=0;t<8;t++){
        float4* hv=(float4*)&s_h[(w*8+t)*HD + l*4];
        *hv = make_float4(acc[t][0],acc[t][1],acc[t][2],acc[t][3]);
    }
    __syncwarp();
    #pragma unroll
    for (int t=0;t<8;t++){acc[t][0]=acc[t][1]=acc[t][2]=acc[t][3]=0.f;}
    {
        const float4* w4=(const float4*)s_w3;
        for (int k=0;k<HD;k++){
            float4 wv = w4[k*32+l];
            #pragma unroll
            for (int t=0;t<8;t++){
                float xv = s_h[(w*8+t)*HD + k];
                acc[t][0]=fmaf(xv,wv.x,acc[t][0]); acc[t][1]=fmaf(xv,wv.y,acc[t][1]);
                acc[t][2]=fmaf(xv,wv.z,acc[t][2]); acc[t][3]=fmaf(xv,wv.w,acc[t][3]);
            }
        }
    }
    {
        float4 bv=((const float4*)hp_b)[l];
        #pragma unroll
        for (int t=0;t<8;t++){
            float4 hv;
            hv.x=tanhf(acc[t][0]+bv.x); hv.y=tanhf(acc[t][1]+bv.y);
            hv.z=tanhf(acc[t][2]+bv.z); hv.w=tanhf(acc[t][3]+bv.w);
            ((float4*)(g_hyp + (size_t)(tokbase + w*8 + t)*HD))[l]=hv;
        }
    }
}

// ======================= prep: xbf + zero scratch + slots init (merged) =======================
__global__ void prep_kernel(const float* __restrict__ x, const float* __restrict__ obj_dirs)
{
    const int bid = blockIdx.x, tid = threadIdx.x;
    int i = bid*256 + tid;
    float2 v = ((const float2*)x)[i];
    g_xbf2[i] = __float22bfloat162_rn(v);

    if (bid < 192){
        g_upd[bid*256 + tid] = 0.f;
    } else if (bid == 192){
        if (tid < BB*NSLOT) g_rowsum[tid] = 0.f;
    } else if (bid == 193){
        const int w=tid>>5, l=tid&31;
        if (w<NOBJ){
            float4 od=((const float4*)(obj_dirs + w*HD))[l];
            float q=od.x*od.x+od.y*od.y+od.z*od.z+od.w*od.w;
            #pragma unroll
            for (int o=16;o;o>>=1) q += __shfl_xor_sync(0xffffffffu,q,o);
            float nrm=sqrtf(q);
            float inv=1.f/fmaxf(nrm,1e-12f);
            float4 dn=make_float4(od.x*inv,od.y*inv,od.z*inv,od.w*inv);
            float qn=q*inv*inv;
            const float radii[3]={0.2f,0.5f,0.8f};
            for (int b=0;b<BB;b++){
                #pragma unroll
                for (int lv=0;lv<3;lv++){
                    float r=radii[lv];
                    ((float4*)(g_slots + (size_t)(b*NSLOT + w*3+lv)*HD))[l] =
                        make_float4(dn.x*r,dn.y*r,dn.z*r,dn.w*r);
                    if (l==0){
                        float s2=qn*r*r;
                        g_s2[b*NSLOT + w*3+lv]=s2;
                        g_sr[b*NSLOT + w*3+lv]=sqrtf(s2);
                    }
                }
            }
        }
    }
}

// ======================= density + feats (merged) =======================
__device__ __forceinline__ void ins6(float t[6], float v){
    if (v < t[5]){
        t[5]=v;
        #pragma unroll
        for (int s=5;s>0;s--){ if (t[s]<t[s-1]){ float tmp=t[s-1]; t[s-1]=t[s]; t[s]=tmp; } }
    }
}

#define JT_STRIDE 72

__global__ void __launch_bounds__(256) densfeats_kernel(float* __restrict__ dens_out)
{
    __shared__ float smf[3200];
    __nv_bfloat16* sxj = (__nv_bfloat16*)smf;
    float* x2s  = smf + (64*JT_STRIDE*2)/4;
    float* cand = smf;                         // [64][49] = 3136 floats
    float* s_dens = smf + 3136;                // [64]

    const int b  = blockIdx.y;
    const int i0 = blockIdx.x * 64;
    const int tid = threadIdx.x, w = tid>>5, lane = tid&31;
    const int g = lane>>2, tg = lane&3;
    const int rg = w & 3;
    const int jh = w >> 2;
    const int r0 = i0 + rg*16 + g;
    const unsigned short* xb = (const unsigned short*)g_xbf2 + (size_t)b*NNP*IND;

    unsigned int A[4][4];
    {
        const unsigned short* xr0 = xb + (size_t)r0*IND;
        const unsigned short* xr1 = xr0 + 8*IND;
        #pragma unroll
        for (int ks=0;ks<4;ks++){
            int kb = ks*16 + tg*2;
            A[ks][0] = *(const unsigned int*)&xr0[kb];
            A[ks][1] = *(const unsigned int*)&xr1[kb];
            A[ks][2] = *(const unsigned int*)&xr0[kb+8];
            A[ks][3] = *(const unsigned int*)&xr1[kb+8];
        }
    }
    float t6[2][6];
    #pragma unroll
    for (int r=0;r<2;r++){
        #pragma unroll
        for (int s=0;s<6;s++) t6[r][s]=1e30f;
    }

    for (int jt=0; jt<32; jt++){
        __syncthreads();
        {
            #pragma unroll
            for (int p=0;p<8;p++){
                int idx = tid + 256*p;
                int row = idx >> 5, c = idx & 31;
                unsigned int v = *(const unsigned int*)&xb[((size_t)(jt*64 + row))*IND + c*2];
                *(unsigned int*)&sxj[row*JT_STRIDE + c*2] = v;
            }
            if (tid < 64) x2s[tid] = g_x2[b*NNP + jt*64 + tid];
        }
        __syncthreads();
        #pragma unroll
        for (int q=0;q<4;q++){
            const int nt = jh*4 + q;
            const int n  = nt*8 + g;
            float c0=0.f,c1=0.f,c2=0.f,c3=0.f;
            #pragma unroll
            for (int ks=0;ks<4;ks++){
                const __nv_bfloat16* bp = &sxj[n*JT_STRIDE + ks*16 + tg*2];
                unsigned int B0 = *(const unsigned int*)bp;
                unsigned int B1 = *(const unsigned int*)(bp+8);
                asm("mma.sync.aligned.m16n8k16.row.col.f32.bf16.bf16.f32 "
                    "{%0,%1,%2,%3}, {%4,%5,%6,%7}, {%8,%9}, {%0,%1,%2,%3};"
                    : "+f"(c0),"+f"(c1),"+f"(c2),"+f"(c3)
                    : "r"(A[ks][0]),"r"(A[ks][1]),"r"(A[ks][2]),"r"(A[ks][3]),
                      "r"(B0),"r"(B1));
            }
            const int lc = nt*8 + tg*2;
            float xa = x2s[lc], xc = x2s[lc+1];
            ins6(t6[0], xa - 2.f*c0); ins6(t6[0], xc - 2.f*c1);
            ins6(t6[1], xa - 2.f*c2); ins6(t6[1], xc - 2.f*c3);
        }
    }
    __syncthreads();
    {
        int lr0 = rg*16 + g;
        int base = jh*24 + tg*6;
        #pragma unroll
        for (int s=0;s<6;s++){
            cand[lr0*49 + base + s]     = t6[0][s];
            cand[(lr0+8)*49 + base + s] = t6[1][s];
        }
    }
    __syncthreads();
    if (tid < 64){
        float u[6]={1e30f,1e30f,1e30f,1e30f,1e30f,1e30f};
        const float* row = &cand[tid*49];
        #pragma unroll 8
        for (int m=0;m<48;m++) ins6(u, row[m]);
        float x2i = g_x2[b*NNP + i0 + tid];
        float md = (sqrtf(fmaxf(x2i+u[1],0.f)) + sqrtf(fmaxf(x2i+u[2],0.f))
                  + sqrtf(fmaxf(x2i+u[3],0.f)) + sqrtf(fmaxf(x2i+u[4],0.f))
                  + sqrtf(fmaxf(x2i+u[5],0.f))) * 0.2f;
        float dv = tanhf(md);
        s_dens[tid] = dv;
        g_density[b*NNP + i0 + tid] = dv;
        dens_out [b*NNP + i0 + tid] = dv;
    }
    __syncthreads();
    // ---- feats phase: this block owns rows i0..i0+63 ----
    #pragma unroll
    for (int t=0;t<8;t++){
        int row = w*8 + t;
        size_t n = (size_t)b*NNP + i0 + row;
        float4 v = ((const float4*)(g_hyp + n*HD))[lane];
        float q = v.x*v.x+v.y*v.y+v.z*v.z+v.w*v.w;
        #pragma unroll
        for (int o=16;o;o>>=1) q += __shfl_xor_sync(0xffffffffu,q,o);
        float fn = fmaxf(sqrtf(q),1e-6f);
        float dens = s_dens[row];
        float tr = (0.3f+0.5f*(1.f-dens))*0.95f;
        float sc = tr/fn;
        ((float4*)(g_feats + n*HD))[lane] = make_float4(v.x*sc,v.y*sc,v.z*sc,v.w*sc);
        if (lane==0){
            float f2=q*sc*sc;
            g_f2[n]=f2; g_fr[n]=sqrtf(f2);
        }
    }
}

// ======================= gh precompute =======================
__global__ void gh_kernel(const float* __restrict__ obj_dirs,
                          const float* __restrict__ gru_wh,
                          const float* __restrict__ gru_bh)
{
    const int o = blockIdx.x;
    const int w = threadIdx.x>>5, l = threadIdx.x&31;
    float4 od = ((const float4*)(obj_dirs + (size_t)o*HD))[l];
    for (int m=0;m<48;m++){
        int r = w*48 + m;
        float4 wv = ((const float4*)(gru_wh + (size_t)r*HD))[l];
        float p = od.x*wv.x + od.y*wv.y + od.z*wv.z + od.w*wv.w;
        #pragma unroll
        for (int of=16;of;of>>=1) p += __shfl_xor_sync(0xffffffffu,p,of);
        if (l==0) g_gh[o*3*HD + r] = p + gru_bh[r];
    }
}

// ======================= attention: two-phase chunked (low-reg) =======================
#define FPAD 132
#define APAD 25
__global__ void __launch_bounds__(256) attn_kernel(const float* __restrict__ rs_ptr,
                                                   float* __restrict__ attn_out)
{
    __shared__ float s_slots[NSLOT*HD];        // 12288 B
    __shared__ float s_feats[32*FPAD];         // 16896 B
    __shared__ float s_attn[32*APAD];          // 3200 B
    __shared__ float s_f2[32], s_fr[32], s_dn[32];
    __shared__ float s_s2[NSLOT], s_sr[NSLOT];
    const int b = blockIdx.x >> 4;
    const int nbase = (blockIdx.x & 15) * 128;
    const int tid=threadIdx.x, w=tid>>5, l=tid&31;
    {
        const float4* ss=(const float4*)(g_slots + (size_t)b*NSLOT*HD);
        float4* sd=(float4*)s_slots;
        for (int i=tid;i<NSLOT*HD/4;i+=256) sd[i]=ss[i];
        if (tid<NSLOT){ s_s2[tid]=g_s2[b*NSLOT+tid]; s_sr[tid]=g_sr[b*NSLOT+tid]; }
    }
    const float rs = *rs_ptr;
    float4 acc0=make_float4(0.f,0.f,0.f,0.f);
    float4 acc1=make_float4(0.f,0.f,0.f,0.f);
    float4 acc2=make_float4(0.f,0.f,0.f,0.f);
    float rsum=0.f;
    const int lvl = (l<NSLOT)? (l - (l/3)*3) : 0;
    const float basel = (lvl==0)?2.f:((lvl==1)?1.f:0.5f);
    const float4* slots4=(const float4*)s_slots;

    for (int ch=0; ch<4; ch++){
        __syncthreads();
        {   // stage 32 tokens of feats + stats
            const int n0 = nbase + ch*32;
            #pragma unroll
            for (int p=0;p<4;p++){
                int i = tid + 256*p;               // 1024 float4
                int row = i>>5, c = i&31;
                ((float4*)&s_feats[row*FPAD])[c] =
                    ((const float4*)(g_feats + ((size_t)b*NNP + n0 + row)*HD))[c];
            }
            if (tid<32){
                size_t off=(size_t)b*NNP + n0 + tid;
                s_f2[tid]=g_f2[off]; s_fr[tid]=g_fr[off]; s_dn[tid]=g_density[off];
            }
        }
        __syncthreads();
        // ---- phase 1: warp w owns tokens w*4..w*4+3 of the chunk ----
        const float s2k = (l<NSLOT)? s_s2[l] : 0.f;
        const float srk = (l<NSLOT)? s_sr[l] : 0.f;
        #pragma unroll
        for (int ii=0;ii<4;ii++){
            const int row = w*4 + ii;
            float4 f = ((const float4*)&s_feats[row*FPAD])[l];
            float f2n=s_f2[row], frn=s_fr[row], dens=s_dn[row];
            float mod = rs*(dens-0.5f);
            float mydot=0.f;
            #pragma unroll
            for (int k=0;k<NSLOT;k++){
                float4 sv=slots4[k*32+l];
                float p = f.x*sv.x+f.y*sv.y+f.z*sv.z+f.w*sv.w;
                p += __shfl_xor_sync(0xffffffffu,p,16);
                p += __shfl_xor_sync(0xffffffffu,p,8);
                p += __shfl_xor_sync(0xffffffffu,p,4);
                p += __shfl_xor_sync(0xffffffffu,p,2);
                p += __shfl_xor_sync(0xffffffffu,p,1);
                if (l==k) mydot=p;
            }
            float logit=-1e30f;
            if (l<NSLOT){
                float diff2 = fmaxf(f2n + s2k - 2.f*mydot, 0.f);
                float xn = fminf(f2n, 1.f-1e-5f);
                float yn = fminf(s2k, 1.f-1e-5f);
                float den = fmaxf((1.f-xn)*(1.f-yn), 1e-6f);
                float arg = fmaxf(1.f + 2.f*diff2/den, 1.f+1e-6f);
                float hd = acoshf(arg);
                float rd = fabsf(frn-srk);
                float scv = fminf(fmaxf(basel+mod,0.3f),3.f);
                logit = (-hd - 3.f*rd)*scv*10.f;   // /TAU
            }
            float m=logit;
            #pragma unroll
            for (int o=16;o;o>>=1) m=fmaxf(m,__shfl_xor_sync(0xffffffffu,m,o));
            float e=(l<NSLOT)? expf(logit-m):0.f;
            float s=e;
            #pragma unroll
            for (int o=16;o;o>>=1) s+=__shfl_xor_sync(0xffffffffu,s,o);
            float a=e/s;
            if (l<NSLOT){
                s_attn[row*APAD + l]=a;
                rsum += a;
            }
        }
        __syncthreads();
        // ---- phase 2a: coalesced attn_out stores ----
        if (tid < 192){
            int k = tid>>3, q = tid&7;
            float4 v;
            v.x = s_attn[(q*4+0)*APAD + k];
            v.y = s_attn[(q*4+1)*APAD + k];
            v.z = s_attn[(q*4+2)*APAD + k];
            v.w = s_attn[(q*4+3)*APAD + k];
            *(float4*)&attn_out[((size_t)b*NSLOT+k)*NNP + nbase + ch*32 + q*4] = v;
        }
        // ---- phase 2b: upd mini-GEMM, 3 (slot,h4) outputs per thread ----
        #pragma unroll
        for (int p=0;p<3;p++){
            int idx = p*256 + tid;
            int k = idx>>5, h4 = idx&31;
            float4 a4 = (p==0)?acc0:((p==1)?acc1:acc2);
            #pragma unroll 8
            for (int n=0;n<32;n++){
                float av = s_attn[n*APAD + k];                 // warp-broadcast
                float4 fv = ((const float4*)&s_feats[n*FPAD])[h4];
                a4.x=fmaf(av,fv.x,a4.x); a4.y=fmaf(av,fv.y,a4.y);
                a4.z=fmaf(av,fv.z,a4.z); a4.w=fmaf(av,fv.w,a4.w);
            }
            if (p==0) acc0=a4; else if (p==1) acc1=a4; else acc2=a4;
        }
    }
    // ---- finalize ----
    if (l<NSLOT) atomicAdd(&g_rowsum[b*NSLOT+l], rsum);
    #pragma unroll
    for (int p=0;p<3;p++){
        int idx = p*256 + tid;
        int k = idx>>5, h4 = idx&31;
        float4 a4 = (p==0)?acc0:((p==1)?acc1:acc2);
        float* up = g_upd + ((size_t)b*NSLOT+k)*HD + h4*4;
        atomicAdd(up+0,a4.x); atomicAdd(up+1,a4.y);
        atomicAdd(up+2,a4.z); atomicAdd(up+3,a4.w);
    }
}

// ======================= GRU + MLP + renorm (warp-row gi, coalesced) =======================
__device__ __forceinline__ float blksum128(float v, volatile float* red){
    #pragma unroll
    for (int o=16;o;o>>=1) v += __shfl_xor_sync(0xffffffffu,v,o);
    __syncthreads();
    if ((threadIdx.x&31)==0) red[threadIdx.x>>5]=v;
    __syncthreads();
    return red[0]+red[1]+red[2]+red[3];
}

__global__ void __launch_bounds__(128) gru_kernel(const float* __restrict__ obj_dirs,
    const float* __restrict__ gru_wi, const float* __restrict__ gru_bi,
    const float* __restrict__ mlp_w1, const float* __restrict__ mlp_b1,
    const float* __restrict__ mlp_w2, const float* __restrict__ mlp_b2,
    const float* __restrict__ norm_g, const float* __restrict__ norm_b,
    float* __restrict__ slots_out)
{
    __shared__ float s_buf[HD];
    __shared__ float s_gi[3*HD];
    __shared__ float s_red[4];
    const int b = blockIdx.x >> 3, o = blockIdx.x & 7;
    const int h = threadIdx.x, w = h>>5, l = h&31;
    float ou=0.f;
    #pragma unroll
    for (int lv=0;lv<3;lv++){
        int k=o*3+lv;
        ou += g_upd[((size_t)b*NSLOT+k)*HD + h] / (g_rowsum[b*NSLOT+k]+1e-8f);
    }
    s_buf[h]=ou; __syncthreads();
    #pragma unroll
    for (int lv=0;lv<3;lv++){
        int k=o*3+lv;
        g_upd[((size_t)b*NSLOT+k)*HD + h]=0.f;
        if (h==lv) g_rowsum[b*NSLOT+k]=0.f;
    }
    {
        float4 ob = ((const float4*)s_buf)[l];
        for (int m=0;m<96;m++){
            int r = w*96 + m;
            float4 wv = ((const float4*)(gru_wi + (size_t)r*HD))[l];
            float p = ob.x*wv.x + ob.y*wv.y + ob.z*wv.z + ob.w*wv.w;
            #pragma unroll
            for (int of=16;of;of>>=1) p += __shfl_xor_sync(0xffffffffu,p,of);
            if (l==0) s_gi[r] = p + gru_bi[r];
        }
    }
    __syncthreads();
    float hr=g_gh[o*3*HD + h], hz=g_gh[o*3*HD + HD + h], hn=g_gh[o*3*HD + 2*HD + h];
    float rr=sigmoidf(s_gi[h]+hr);
    float z =sigmoidf(s_gi[HD+h]+hz);
    float nnv=tanhf(s_gi[2*HD+h]+rr*hn);
    float oldh=obj_dirs[o*HD+h];
    float nd=(1.f-z)*nnv + z*oldh;
    float s = blksum128(nd, s_red);
    float q = blksum128(nd*nd, s_red);
    float mu=s*(1.f/HD), var=q*(1.f/HD)-mu*mu;
    float ln=(nd-mu)*rsqrtf(var+1e-5f)*norm_g[h]+norm_b[h];
    __syncthreads(); s_buf[h]=ln; __syncthreads();
    float m1=mlp_b1[h];
    {
        const float* w1=mlp_w1;
        #pragma unroll 8
        for (int hh=0;hh<HD;hh++) m1=fmaf(s_buf[hh],w1[(size_t)hh*HD+h],m1);
    }
    m1=geluf(m1);
    __syncthreads(); s_buf[h]=m1; __syncthreads();
    float m2=mlp_b2[h];
    {
        const float* w2=mlp_w2;
        #pragma unroll 8
        for (int hh=0;hh<HD;hh++) m2=fmaf(s_buf[hh],w2[(size_t)hh*HD+h],m2);
    }
    float nd2 = nd + 0.2f*m2;
    float q2 = blksum128(nd2*nd2, s_red);
    float nrm = fmaxf(sqrtf(q2),1e-12f);
    float ndn = nd2/nrm;
    float qn = q2/(nrm*nrm);
    const float radii[3]={0.2f,0.5f,0.8f};
    #pragma unroll
    for (int lv=0;lv<3;lv++){
        float r=radii[lv];
        float v=ndn*r;
        size_t idx=((size_t)b*NSLOT + o*3+lv)*HD + h;
        g_slots[idx]=v;
        slots_out[idx]=v;
    }
    if (h<3){
        float r=radii[h];
        float s2v=qn*r*r;
        g_s2[b*NSLOT + o*3 + h]=s2v;
        g_sr[b*NSLOT + o*3 + h]=sqrtf(s2v);
    }
}

// ======================= host launch =======================
extern "C" void kernel_launch(void* const* d_in, const int* in_sizes, int n_in,
                              void* d_out, int out_size)
{
    const float* x      = (const float*)d_in[0];
    const float* fe_w1  = (const float*)d_in[1];
    const float* fe_b1  = (const float*)d_in[2];
    const float* ln1_g  = (const float*)d_in[3];
    const float* ln1_b  = (const float*)d_in[4];
    const float* fe_w2  = (const float*)d_in[5];
    const float* fe_b2  = (const float*)d_in[6];
    const float* ln2_g  = (const float*)d_in[7];
    const float* ln2_b  = (const float*)d_in[8];
    const float* hp_w   = (const float*)d_in[9];
    const float* hp_b   = (const float*)d_in[10];
    const float* obj_dirs = (const float*)d_in[11];
    const float* radius_scale = (const float*)d_in[12];
    const float* gru_wi = (const float*)d_in[13];
    const float* gru_wh = (const float*)d_in[14];
    const float* gru_bi = (const float*)d_in[15];
    const float* gru_bh = (const float*)d_in[16];
    const float* mlp_w1 = (const float*)d_in[17];
    const float* mlp_b1 = (const float*)d_in[18];
    const float* mlp_w2 = (const float*)d_in[19];
    const float* mlp_b2 = (const float*)d_in[20];
    const float* norm_g = (const float*)d_in[21];
    const float* norm_b = (const float*)d_in[22];

    float* out = (float*)d_out;
    float* slots_out = out;                                   // [16,24,128]
    float* attn_out  = out + BB*NSLOT*HD;                     // [16,24,2048]
    float* dens_out  = attn_out + (size_t)BB*NSLOT*NNP;       // [16,2048]

    size_t encSmem = (size_t)ENC_SMEM_FLOATS*sizeof(float);   // 212,992 B
    cudaFuncSetAttribute(enc_kernel, cudaFuncAttributeMaxDynamicSharedMemorySize, (int)encSmem);

    // Launch order: attn_kernel is the 0-based 4th launch (ncu capture point).
    enc_kernel<<<BB*NNP/64, 256, encSmem>>>(x, fe_w1, fe_b1, ln1_g, ln1_b,
                                            fe_w2, fe_b2, ln2_g, ln2_b, hp_w, hp_b);   // 0
    prep_kernel<<<BB*NNP*IND/2/256, 256>>>(x, obj_dirs);                               // 1
    {
        dim3 g(NNP/64, BB);
        densfeats_kernel<<<g, 256>>>(dens_out);                                        // 2
    }
    attn_kernel<<<BB*16, 256>>>(radius_scale, attn_out);                               // 3 <- profiled
    gh_kernel<<<NOBJ, 256>>>(obj_dirs, gru_wh, gru_bh);                                // 4
    gru_kernel<<<BB*NOBJ, 128>>>(obj_dirs, gru_wi, gru_bi,
                                 mlp_w1, mlp_b1, mlp_w2, mlp_b2,
                                 norm_g, norm_b, slots_out);                           // 5
    for (int it=1; it<NITER; it++){
        attn_kernel<<<BB*16, 256>>>(radius_scale, attn_out);
        gru_kernel<<<BB*NOBJ, 128>>>(obj_dirs, gru_wi, gru_bi,
                                     mlp_w1, mlp_b1, mlp_w2, mlp_b2,
                                     norm_g, norm_b, slots_out);
    }
}

// round 14
// speedup vs baseline: 1.2439x; 1.0744x over previous
#include <cuda_runtime.h>
#include <cuda_bf16.h>
#include <math.h>

#define BB 16
#define NNP 2048
#define IND 64
#define HD 128
#define NOBJ 8
#define NSLOT 24
#define NITER 3

// ---------------- device scratch (static, no allocation) ----------------
__device__ float g_hyp[BB*NNP*HD];
__device__ float g_feats[BB*NNP*HD];
__device__ float g_x2[BB*NNP];
__device__ float g_f2[BB*NNP];
__device__ float g_fr[BB*NNP];
__device__ float g_density[BB*NNP];
__device__ float g_slots[BB*NSLOT*HD];
__device__ float g_s2[BB*NSLOT];
__device__ float g_sr[BB*NSLOT];
__device__ float g_gh[NOBJ*3*HD];
__device__ float g_upd[BB*NSLOT*HD];
__device__ float g_rowsum[BB*NSLOT];
__device__ __nv_bfloat162 g_xbf2[BB*NNP*IND/2];

__device__ __forceinline__ float geluf(float x){
    return 0.5f*x*(1.f+erff(x*0.70710678118654752f));
}
__device__ __forceinline__ float sigmoidf(float x){
    return 1.f/(1.f+expf(-x));
}

// ======================= encoder (resident weights) =======================
#define ENC_SMEM_FLOATS (IND*HD + HD*HD + HD*HD + 64*IND + 64*HD)   // 212,992 B

__global__ void __launch_bounds__(256) enc_kernel(const float* __restrict__ x,
    const float* __restrict__ fe_w1, const float* __restrict__ fe_b1,
    const float* __restrict__ ln1_g, const float* __restrict__ ln1_b,
    const float* __restrict__ fe_w2, const float* __restrict__ fe_b2,
    const float* __restrict__ ln2_g, const float* __restrict__ ln2_b,
    const float* __restrict__ hp_w,  const float* __restrict__ hp_b)
{
    extern __shared__ float sm[];
    float* s_w1 = sm;
    float* s_w2 = s_w1 + IND*HD;
    float* s_w3 = s_w2 + HD*HD;
    float* s_x  = s_w3 + HD*HD;
    float* s_h  = s_x  + 64*IND;

    const int tid = threadIdx.x;
    const int tokbase = blockIdx.x*64;
    {
        const float4* a=(const float4*)fe_w1; float4* d1=(float4*)s_w1;
        for (int i=tid;i<IND*HD/4;i+=256) d1[i]=a[i];
        const float4* b=(const float4*)fe_w2; float4* d2=(float4*)s_w2;
        for (int i=tid;i<HD*HD/4;i+=256) d2[i]=b[i];
        const float4* c=(const float4*)hp_w; float4* d3=(float4*)s_w3;
        for (int i=tid;i<HD*HD/4;i+=256) d3[i]=c[i];
        const float4* xs=(const float4*)(x + (size_t)tokbase*IND); float4* xd=(float4*)s_x;
        for (int i=tid;i<64*IND/4;i+=256) xd[i]=xs[i];
    }
    __syncthreads();
    if (tid < 64){
        float s=0.f;
        #pragma unroll 8
        for (int k=0;k<IND;k++){ float v=s_x[tid*IND+k]; s+=v*v; }
        g_x2[tokbase+tid]=s;
    }
    const int w = tid>>5, l = tid&31;

    float acc[8][4];
    #pragma unroll
    for (int t=0;t<8;t++){acc[t][0]=acc[t][1]=acc[t][2]=acc[t][3]=0.f;}
    {
        const float4* w4=(const float4*)s_w1;
        for (int k=0;k<IND;k++){
            float4 wv = w4[k*32+l];
            #pragma unroll
            for (int t=0;t<8;t++){
                float xv = s_x[(w*8+t)*IND + k];
                acc[t][0]=fmaf(xv,wv.x,acc[t][0]); acc[t][1]=fmaf(xv,wv.y,acc[t][1]);
                acc[t][2]=fmaf(xv,wv.z,acc[t][2]); acc[t][3]=fmaf(xv,wv.w,acc[t][3]);
            }
        }
    }
    {
        float4 bv=((const float4*)fe_b1)[l];
        float4 gv=((const float4*)ln1_g)[l];
        float4 bt=((const float4*)ln1_b)[l];
        #pragma unroll
        for (int t=0;t<8;t++){
            float v0=acc[t][0]+bv.x, v1=acc[t][1]+bv.y, v2=acc[t][2]+bv.z, v3=acc[t][3]+bv.w;
            float s=v0+v1+v2+v3, q=v0*v0+v1*v1+v2*v2+v3*v3;
            #pragma unroll
            for (int o=16;o;o>>=1){ s+=__shfl_xor_sync(0xffffffffu,s,o); q+=__shfl_xor_sync(0xffffffffu,q,o); }
            float mu=s*(1.f/HD), var=q*(1.f/HD)-mu*mu;
            float inv=rsqrtf(var+1e-5f);
            v0=geluf((v0-mu)*inv*gv.x+bt.x); v1=geluf((v1-mu)*inv*gv.y+bt.y);
            v2=geluf((v2-mu)*inv*gv.z+bt.z); v3=geluf((v3-mu)*inv*gv.w+bt.w);
            float4* hv=(float4*)&s_h[(w*8+t)*HD + l*4];
            *hv = make_float4(v0,v1,v2,v3);
        }
    }
    __syncwarp();
    #pragma unroll
    for (int t=0;t<8;t++){acc[t][0]=acc[t][1]=acc[t][2]=acc[t][3]=0.f;}
    {
        const float4* w4=(const float4*)s_w2;
        for (int k=0;k<HD;k++){
            float4 wv = w4[k*32+l];
            #pragma unroll
            for (int t=0;t<8;t++){
                float xv = s_h[(w*8+t)*HD + k];
                acc[t][0]=fmaf(xv,wv.x,acc[t][0]); acc[t][1]=fmaf(xv,wv.y,acc[t][1]);
                acc[t][2]=fmaf(xv,wv.z,acc[t][2]); acc[t][3]=fmaf(xv,wv.w,acc[t][3]);
            }
        }
    }
    {
        float4 bv=((const float4*)fe_b2)[l];
        float4 gv=((const float4*)ln2_g)[l];
        float4 bt=((const float4*)ln2_b)[l];
        #pragma unroll
        for (int t=0;t<8;t++){
            float v0=acc[t][0]+bv.x, v1=acc[t][1]+bv.y, v2=acc[t][2]+bv.z, v3=acc[t][3]+bv.w;
            float s=v0+v1+v2+v3, q=v0*v0+v1*v1+v2*v2+v3*v3;
            #pragma unroll
            for (int o=16;o;o>>=1){ s+=__shfl_xor_sync(0xffffffffu,s,o); q+=__shfl_xor_sync(0xffffffffu,q,o); }
            float mu=s*(1.f/HD), var=q*(1.f/HD)-mu*mu;
            float inv=rsqrtf(var+1e-5f);
            acc[t][0]=(v0-mu)*inv*gv.x+bt.x; acc[t][1]=(v1-mu)*inv*gv.y+bt.y;
            acc[t][2]=(v2-mu)*inv*gv.z+bt.z; acc[t][3]=(v3-mu)*inv*gv.w+bt.w;
        }
    }
    __syncwarp();
    #pragma unroll
    for (int t=0;t<8;t++){
        float4* hv=(float4*)&s_h[(w*8+t)*HD + l*4];
        *hv = make_float4(acc[t][0],acc[t][1],acc[t][2],acc[t][3]);
    }
    __syncwarp();
    #pragma unroll
    for (int t=0;t<8;t++){acc[t][0]=acc[t][1]=acc[t][2]=acc[t][3]=0.f;}
    {
        const float4* w4=(const float4*)s_w3;
        for (int k=0;k<HD;k++){
            float4 wv = w4[k*32+l];
            #pragma unroll
            for (int t=0;t<8;t++){
                float xv = s_h[(w*8+t)*HD + k];
                acc[t][0]=fmaf(xv,wv.x,acc[t][0]); acc[t][1]=fmaf(xv,wv.y,acc[t][1]);
                acc[t][2]=fmaf(xv,wv.z,acc[t][2]); acc[t][3]=fmaf(xv,wv.w,acc[t][3]);
            }
        }
    }
    {
        float4 bv=((const float4*)hp_b)[l];
        #pragma unroll
        for (int t=0;t<8;t++){
            float4 hv;
            hv.x=tanhf(acc[t][0]+bv.x); hv.y=tanhf(acc[t][1]+bv.y);
            hv.z=tanhf(acc[t][2]+bv.z); hv.w=tanhf(acc[t][3]+bv.w);
            ((float4*)(g_hyp + (size_t)(tokbase + w*8 + t)*HD))[l]=hv;
        }
    }
}

// ======================= prep: xbf + zero scratch + slots init (merged) =======================
__global__ void prep_kernel(const float* __restrict__ x, const float* __restrict__ obj_dirs)
{
    const int bid = blockIdx.x, tid = threadIdx.x;
    int i = bid*256 + tid;
    float2 v = ((const float2*)x)[i];
    g_xbf2[i] = __float22bfloat162_rn(v);

    if (bid < 192){
        g_upd[bid*256 + tid] = 0.f;
    } else if (bid == 192){
        if (tid < BB*NSLOT) g_rowsum[tid] = 0.f;
    } else if (bid == 193){
        const int w=tid>>5, l=tid&31;
        if (w<NOBJ){
            float4 od=((const float4*)(obj_dirs + w*HD))[l];
            float q=od.x*od.x+od.y*od.y+od.z*od.z+od.w*od.w;
            #pragma unroll
            for (int o=16;o;o>>=1) q += __shfl_xor_sync(0xffffffffu,q,o);
            float nrm=sqrtf(q);
            float inv=1.f/fmaxf(nrm,1e-12f);
            float4 dn=make_float4(od.x*inv,od.y*inv,od.z*inv,od.w*inv);
            float qn=q*inv*inv;
            const float radii[3]={0.2f,0.5f,0.8f};
            for (int b=0;b<BB;b++){
                #pragma unroll
                for (int lv=0;lv<3;lv++){
                    float r=radii[lv];
                    ((float4*)(g_slots + (size_t)(b*NSLOT + w*3+lv)*HD))[l] =
                        make_float4(dn.x*r,dn.y*r,dn.z*r,dn.w*r);
                    if (l==0){
                        float s2=qn*r*r;
                        g_s2[b*NSLOT + w*3+lv]=s2;
                        g_sr[b*NSLOT + w*3+lv]=sqrtf(s2);
                    }
                }
            }
        }
    }
}

// ======================= density + feats (merged) =======================
__device__ __forceinline__ void ins6(float t[6], float v){
    if (v < t[5]){
        t[5]=v;
        #pragma unroll
        for (int s=5;s>0;s--){ if (t[s]<t[s-1]){ float tmp=t[s-1]; t[s-1]=t[s]; t[s]=tmp; } }
    }
}

#define JT_STRIDE 72

__global__ void __launch_bounds__(256) densfeats_kernel(float* __restrict__ dens_out)
{
    __shared__ float smf[3200];
    __nv_bfloat16* sxj = (__nv_bfloat16*)smf;
    float* x2s  = smf + (64*JT_STRIDE*2)/4;
    float* cand = smf;                         // [64][49] = 3136 floats
    float* s_dens = smf + 3136;                // [64]

    const int b  = blockIdx.y;
    const int i0 = blockIdx.x * 64;
    const int tid = threadIdx.x, w = tid>>5, lane = tid&31;
    const int g = lane>>2, tg = lane&3;
    const int rg = w & 3;
    const int jh = w >> 2;
    const int r0 = i0 + rg*16 + g;
    const unsigned short* xb = (const unsigned short*)g_xbf2 + (size_t)b*NNP*IND;

    unsigned int A[4][4];
    {
        const unsigned short* xr0 = xb + (size_t)r0*IND;
        const unsigned short* xr1 = xr0 + 8*IND;
        #pragma unroll
        for (int ks=0;ks<4;ks++){
            int kb = ks*16 + tg*2;
            A[ks][0] = *(const unsigned int*)&xr0[kb];
            A[ks][1] = *(const unsigned int*)&xr1[kb];
            A[ks][2] = *(const unsigned int*)&xr0[kb+8];
            A[ks][3] = *(const unsigned int*)&xr1[kb+8];
        }
    }
    float t6[2][6];
    #pragma unroll
    for (int r=0;r<2;r++){
        #pragma unroll
        for (int s=0;s<6;s++) t6[r][s]=1e30f;
    }

    for (int jt=0; jt<32; jt++){
        __syncthreads();
        {
            #pragma unroll
            for (int p=0;p<8;p++){
                int idx = tid + 256*p;
                int row = idx >> 5, c = idx & 31;
                unsigned int v = *(const unsigned int*)&xb[((size_t)(jt*64 + row))*IND + c*2];
                *(unsigned int*)&sxj[row*JT_STRIDE + c*2] = v;
            }
            if (tid < 64) x2s[tid] = g_x2[b*NNP + jt*64 + tid];
        }
        __syncthreads();
        #pragma unroll
        for (int q=0;q<4;q++){
            const int nt = jh*4 + q;
            const int n  = nt*8 + g;
            float c0=0.f,c1=0.f,c2=0.f,c3=0.f;
            #pragma unroll
            for (int ks=0;ks<4;ks++){
                const __nv_bfloat16* bp = &sxj[n*JT_STRIDE + ks*16 + tg*2];
                unsigned int B0 = *(const unsigned int*)bp;
                unsigned int B1 = *(const unsigned int*)(bp+8);
                asm("mma.sync.aligned.m16n8k16.row.col.f32.bf16.bf16.f32 "
                    "{%0,%1,%2,%3}, {%4,%5,%6,%7}, {%8,%9}, {%0,%1,%2,%3};"
                    : "+f"(c0),"+f"(c1),"+f"(c2),"+f"(c3)
                    : "r"(A[ks][0]),"r"(A[ks][1]),"r"(A[ks][2]),"r"(A[ks][3]),
                      "r"(B0),"r"(B1));
            }
            const int lc = nt*8 + tg*2;
            float xa = x2s[lc], xc = x2s[lc+1];
            ins6(t6[0], xa - 2.f*c0); ins6(t6[0], xc - 2.f*c1);
            ins6(t6[1], xa - 2.f*c2); ins6(t6[1], xc - 2.f*c3);
        }
    }
    __syncthreads();
    {
        int lr0 = rg*16 + g;
        int base = jh*24 + tg*6;
        #pragma unroll
        for (int s=0;s<6;s++){
            cand[lr0*49 + base + s]     = t6[0][s];
            cand[(lr0+8)*49 + base + s] = t6[1][s];
        }
    }
    __syncthreads();
    if (tid < 64){
        float u[6]={1e30f,1e30f,1e30f,1e30f,1e30f,1e30f};
        const float* row = &cand[tid*49];
        #pragma unroll 8
        for (int m=0;m<48;m++) ins6(u, row[m]);
        float x2i = g_x2[b*NNP + i0 + tid];
        float md = (sqrtf(fmaxf(x2i+u[1],0.f)) + sqrtf(fmaxf(x2i+u[2],0.f))
                  + sqrtf(fmaxf(x2i+u[3],0.f)) + sqrtf(fmaxf(x2i+u[4],0.f))
                  + sqrtf(fmaxf(x2i+u[5],0.f))) * 0.2f;
        float dv = tanhf(md);
        s_dens[tid] = dv;
        g_density[b*NNP + i0 + tid] = dv;
        dens_out [b*NNP + i0 + tid] = dv;
    }
    __syncthreads();
    // ---- feats phase ----
    #pragma unroll
    for (int t=0;t<8;t++){
        int row = w*8 + t;
        size_t n = (size_t)b*NNP + i0 + row;
        float4 v = ((const float4*)(g_hyp + n*HD))[lane];
        float q = v.x*v.x+v.y*v.y+v.z*v.z+v.w*v.w;
        #pragma unroll
        for (int o=16;o;o>>=1) q += __shfl_xor_sync(0xffffffffu,q,o);
        float fn = fmaxf(sqrtf(q),1e-6f);
        float dens = s_dens[row];
        float tr = (0.3f+0.5f*(1.f-dens))*0.95f;
        float sc = tr/fn;
        ((float4*)(g_feats + n*HD))[lane] = make_float4(v.x*sc,v.y*sc,v.z*sc,v.w*sc);
        if (lane==0){
            float f2=q*sc*sc;
            g_f2[n]=f2; g_fr[n]=sqrtf(f2);
        }
    }
}

// ======================= gh precompute =======================
__global__ void gh_kernel(const float* __restrict__ obj_dirs,
                          const float* __restrict__ gru_wh,
                          const float* __restrict__ gru_bh)
{
    const int o = blockIdx.x;
    const int w = threadIdx.x>>5, l = threadIdx.x&31;
    float4 od = ((const float4*)(obj_dirs + (size_t)o*HD))[l];
    for (int m=0;m<48;m++){
        int r = w*48 + m;
        float4 wv = ((const float4*)(gru_wh + (size_t)r*HD))[l];
        float p = od.x*wv.x + od.y*wv.y + od.z*wv.z + od.w*wv.w;
        #pragma unroll
        for (int of=16;of;of>>=1) p += __shfl_xor_sync(0xffffffffu,p,of);
        if (l==0) g_gh[o*3*HD + r] = p + gru_bh[r];
    }
}

// ======================= attention: two-phase chunked, 2 blocks/SM =======================
#define FPAD 132
#define APAD 25
__global__ void __launch_bounds__(256,2) attn_kernel(const float* __restrict__ rs_ptr,
                                                     float* __restrict__ attn_out)
{
    __shared__ float s_slots[NSLOT*HD];        // 12288 B
    __shared__ float s_feats[32*FPAD];         // 16896 B
    __shared__ float s_attn[32*APAD];          // 3200 B
    __shared__ float s_f2[32], s_fr[32], s_dn[32];
    __shared__ float s_s2[NSLOT], s_sr[NSLOT];
    const int b = blockIdx.x >> 4;
    const int nbase = (blockIdx.x & 15) * 128;
    const int tid=threadIdx.x, w=tid>>5, l=tid&31;
    {
        const float4* ss=(const float4*)(g_slots + (size_t)b*NSLOT*HD);
        float4* sd=(float4*)s_slots;
        for (int i=tid;i<NSLOT*HD/4;i+=256) sd[i]=ss[i];
        if (tid<NSLOT){ s_s2[tid]=g_s2[b*NSLOT+tid]; s_sr[tid]=g_sr[b*NSLOT+tid]; }
    }
    const float rs = *rs_ptr;
    float4 acc0=make_float4(0.f,0.f,0.f,0.f);
    float4 acc1=make_float4(0.f,0.f,0.f,0.f);
    float4 acc2=make_float4(0.f,0.f,0.f,0.f);
    float rsum=0.f;
    const int lvl = (l<NSLOT)? (l - (l/3)*3) : 0;
    const float basel = (lvl==0)?2.f:((lvl==1)?1.f:0.5f);
    const float4* slots4=(const float4*)s_slots;

    for (int ch=0; ch<4; ch++){
        __syncthreads();
        {   // stage 32 tokens of feats + stats
            const int n0 = nbase + ch*32;
            #pragma unroll
            for (int p=0;p<4;p++){
                int i = tid + 256*p;               // 1024 float4
                int row = i>>5, c = i&31;
                ((float4*)&s_feats[row*FPAD])[c] =
                    ((const float4*)(g_feats + ((size_t)b*NNP + n0 + row)*HD))[c];
            }
            if (tid<32){
                size_t off=(size_t)b*NNP + n0 + tid;
                s_f2[tid]=g_f2[off]; s_fr[tid]=g_fr[off]; s_dn[tid]=g_density[off];
            }
        }
        __syncthreads();
        // ---- phase 1: warp w owns tokens w*4..w*4+3 (unroll 1 to cap live ranges) ----
        const float s2k = (l<NSLOT)? s_s2[l] : 0.f;
        const float srk = (l<NSLOT)? s_sr[l] : 0.f;
        #pragma unroll 1
        for (int ii=0;ii<4;ii++){
            const int row = w*4 + ii;
            float4 f = ((const float4*)&s_feats[row*FPAD])[l];
            float f2n=s_f2[row], frn=s_fr[row], dens=s_dn[row];
            float mod = rs*(dens-0.5f);
            float mydot=0.f;
            #pragma unroll
            for (int k=0;k<NSLOT;k++){
                float4 sv=slots4[k*32+l];
                float p = f.x*sv.x+f.y*sv.y+f.z*sv.z+f.w*sv.w;
                p += __shfl_xor_sync(0xffffffffu,p,16);
                p += __shfl_xor_sync(0xffffffffu,p,8);
                p += __shfl_xor_sync(0xffffffffu,p,4);
                p += __shfl_xor_sync(0xffffffffu,p,2);
                p += __shfl_xor_sync(0xffffffffu,p,1);
                if (l==k) mydot=p;
            }
            float logit=-1e30f;
            if (l<NSLOT){
                float diff2 = fmaxf(f2n + s2k - 2.f*mydot, 0.f);
                float xn = fminf(f2n, 1.f-1e-5f);
                float yn = fminf(s2k, 1.f-1e-5f);
                float den = fmaxf((1.f-xn)*(1.f-yn), 1e-6f);
                float arg = fmaxf(1.f + 2.f*diff2/den, 1.f+1e-6f);
                float hd = acoshf(arg);
                float rd = fabsf(frn-srk);
                float scv = fminf(fmaxf(basel+mod,0.3f),3.f);
                logit = (-hd - 3.f*rd)*scv*10.f;   // /TAU
            }
            float m=logit;
            #pragma unroll
            for (int o=16;o;o>>=1) m=fmaxf(m,__shfl_xor_sync(0xffffffffu,m,o));
            float e=(l<NSLOT)? expf(logit-m):0.f;
            float s=e;
            #pragma unroll
            for (int o=16;o;o>>=1) s+=__shfl_xor_sync(0xffffffffu,s,o);
            float a=e/s;
            if (l<NSLOT){
                s_attn[row*APAD + l]=a;
                rsum += a;
            }
        }
        __syncthreads();
        // ---- phase 2a: coalesced attn_out stores ----
        if (tid < 192){
            int k = tid>>3, q = tid&7;
            float4 v;
            v.x = s_attn[(q*4+0)*APAD + k];
            v.y = s_attn[(q*4+1)*APAD + k];
            v.z = s_attn[(q*4+2)*APAD + k];
            v.w = s_attn[(q*4+3)*APAD + k];
            *(float4*)&attn_out[((size_t)b*NSLOT+k)*NNP + nbase + ch*32 + q*4] = v;
        }
        // ---- phase 2b: upd mini-GEMM, 3 (slot,h4) outputs per thread ----
        #pragma unroll
        for (int p=0;p<3;p++){
            int idx = p*256 + tid;
            int k = idx>>5, h4 = idx&31;
            float4 a4 = (p==0)?acc0:((p==1)?acc1:acc2);
            #pragma unroll 8
            for (int n=0;n<32;n++){
                float av = s_attn[n*APAD + k];                 // warp-broadcast
                float4 fv = ((const float4*)&s_feats[n*FPAD])[h4];
                a4.x=fmaf(av,fv.x,a4.x); a4.y=fmaf(av,fv.y,a4.y);
                a4.z=fmaf(av,fv.z,a4.z); a4.w=fmaf(av,fv.w,a4.w);
            }
            if (p==0) acc0=a4; else if (p==1) acc1=a4; else acc2=a4;
        }
    }
    // ---- finalize ----
    if (l<NSLOT) atomicAdd(&g_rowsum[b*NSLOT+l], rsum);
    #pragma unroll
    for (int p=0;p<3;p++){
        int idx = p*256 + tid;
        int k = idx>>5, h4 = idx&31;
        float4 a4 = (p==0)?acc0:((p==1)?acc1:acc2);
        float* up = g_upd + ((size_t)b*NSLOT+k)*HD + h4*4;
        atomicAdd(up+0,a4.x); atomicAdd(up+1,a4.y);
        atomicAdd(up+2,a4.z); atomicAdd(up+3,a4.w);
    }
}

// ======================= GRU + MLP + renorm (warp-row gi, coalesced) =======================
__device__ __forceinline__ float blksum128(float v, volatile float* red){
    #pragma unroll
    for (int o=16;o;o>>=1) v += __shfl_xor_sync(0xffffffffu,v,o);
    __syncthreads();
    if ((threadIdx.x&31)==0) red[threadIdx.x>>5]=v;
    __syncthreads();
    return red[0]+red[1]+red[2]+red[3];
}

__global__ void __launch_bounds__(128) gru_kernel(const float* __restrict__ obj_dirs,
    const float* __restrict__ gru_wi, const float* __restrict__ gru_bi,
    const float* __restrict__ mlp_w1, const float* __restrict__ mlp_b1,
    const float* __restrict__ mlp_w2, const float* __restrict__ mlp_b2,
    const float* __restrict__ norm_g, const float* __restrict__ norm_b,
    float* __restrict__ slots_out)
{
    __shared__ float s_buf[HD];
    __shared__ float s_gi[3*HD];
    __shared__ float s_red[4];
    const int b = blockIdx.x >> 3, o = blockIdx.x & 7;
    const int h = threadIdx.x, w = h>>5, l = h&31;
    float ou=0.f;
    #pragma unroll
    for (int lv=0;lv<3;lv++){
        int k=o*3+lv;
        ou += g_upd[((size_t)b*NSLOT+k)*HD + h] / (g_rowsum[b*NSLOT+k]+1e-8f);
    }
    s_buf[h]=ou; __syncthreads();
    #pragma unroll
    for (int lv=0;lv<3;lv++){
        int k=o*3+lv;
        g_upd[((size_t)b*NSLOT+k)*HD + h]=0.f;
        if (h==lv) g_rowsum[b*NSLOT+k]=0.f;
    }
    {
        float4 ob = ((const float4*)s_buf)[l];
        for (int m=0;m<96;m++){
            int r = w*96 + m;
            float4 wv = ((const float4*)(gru_wi + (size_t)r*HD))[l];
            float p = ob.x*wv.x + ob.y*wv.y + ob.z*wv.z + ob.w*wv.w;
            #pragma unroll
            for (int of=16;of;of>>=1) p += __shfl_xor_sync(0xffffffffu,p,of);
            if (l==0) s_gi[r] = p + gru_bi[r];
        }
    }
    __syncthreads();
    float hr=g_gh[o*3*HD + h], hz=g_gh[o*3*HD + HD + h], hn=g_gh[o*3*HD + 2*HD + h];
    float rr=sigmoidf(s_gi[h]+hr);
    float z =sigmoidf(s_gi[HD+h]+hz);
    float nnv=tanhf(s_gi[2*HD+h]+rr*hn);
    float oldh=obj_dirs[o*HD+h];
    float nd=(1.f-z)*nnv + z*oldh;
    float s = blksum128(nd, s_red);
    float q = blksum128(nd*nd, s_red);
    float mu=s*(1.f/HD), var=q*(1.f/HD)-mu*mu;
    float ln=(nd-mu)*rsqrtf(var+1e-5f)*norm_g[h]+norm_b[h];
    __syncthreads(); s_buf[h]=ln; __syncthreads();
    float m1=mlp_b1[h];
    {
        const float* w1=mlp_w1;
        #pragma unroll 8
        for (int hh=0;hh<HD;hh++) m1=fmaf(s_buf[hh],w1[(size_t)hh*HD+h],m1);
    }
    m1=geluf(m1);
    __syncthreads(); s_buf[h]=m1; __syncthreads();
    float m2=mlp_b2[h];
    {
        const float* w2=mlp_w2;
        #pragma unroll 8
        for (int hh=0;hh<HD;hh++) m2=fmaf(s_buf[hh],w2[(size_t)hh*HD+h],m2);
    }
    float nd2 = nd + 0.2f*m2;
    float q2 = blksum128(nd2*nd2, s_red);
    float nrm = fmaxf(sqrtf(q2),1e-12f);
    float ndn = nd2/nrm;
    float qn = q2/(nrm*nrm);
    const float radii[3]={0.2f,0.5f,0.8f};
    #pragma unroll
    for (int lv=0;lv<3;lv++){
        float r=radii[lv];
        float v=ndn*r;
        size_t idx=((size_t)b*NSLOT + o*3+lv)*HD + h;
        g_slots[idx]=v;
        slots_out[idx]=v;
    }
    if (h<3){
        float r=radii[h];
        float s2v=qn*r*r;
        g_s2[b*NSLOT + o*3 + h]=s2v;
        g_sr[b*NSLOT + o*3 + h]=sqrtf(s2v);
    }
}

// ======================= host launch =======================
extern "C" void kernel_launch(void* const* d_in, const int* in_sizes, int n_in,
                              void* d_out, int out_size)
{
    const float* x      = (const float*)d_in[0];
    const float* fe_w1  = (const float*)d_in[1];
    const float* fe_b1  = (const float*)d_in[2];
    const float* ln1_g  = (const float*)d_in[3];
    const float* ln1_b  = (const float*)d_in[4];
    const float* fe_w2  = (const float*)d_in[5];
    const float* fe_b2  = (const float*)d_in[6];
    const float* ln2_g  = (const float*)d_in[7];
    const float* ln2_b  = (const float*)d_in[8];
    const float* hp_w   = (const float*)d_in[9];
    const float* hp_b   = (const float*)d_in[10];
    const float* obj_dirs = (const float*)d_in[11];
    const float* radius_scale = (const float*)d_in[12];
    const float* gru_wi = (const float*)d_in[13];
    const float* gru_wh = (const float*)d_in[14];
    const float* gru_bi = (const float*)d_in[15];
    const float* gru_bh = (const float*)d_in[16];
    const float* mlp_w1 = (const float*)d_in[17];
    const float* mlp_b1 = (const float*)d_in[18];
    const float* mlp_w2 = (const float*)d_in[19];
    const float* mlp_b2 = (const float*)d_in[20];
    const float* norm_g = (const float*)d_in[21];
    const float* norm_b = (const float*)d_in[22];

    float* out = (float*)d_out;
    float* slots_out = out;                                   // [16,24,128]
    float* attn_out  = out + BB*NSLOT*HD;                     // [16,24,2048]
    float* dens_out  = attn_out + (size_t)BB*NSLOT*NNP;       // [16,2048]

    size_t encSmem = (size_t)ENC_SMEM_FLOATS*sizeof(float);   // 212,992 B
    cudaFuncSetAttribute(enc_kernel, cudaFuncAttributeMaxDynamicSharedMemorySize, (int)encSmem);

    // Launch order: attn_kernel is the 0-based 4th launch (ncu capture point).
    enc_kernel<<<BB*NNP/64, 256, encSmem>>>(x, fe_w1, fe_b1, ln1_g, ln1_b,
                                            fe_w2, fe_b2, ln2_g, ln2_b, hp_w, hp_b);   // 0
    prep_kernel<<<BB*NNP*IND/2/256, 256>>>(x, obj_dirs);                               // 1
    {
        dim3 g(NNP/64, BB);
        densfeats_kernel<<<g, 256>>>(dens_out);                                        // 2
    }
    attn_kernel<<<BB*16, 256>>>(radius_scale, attn_out);                               // 3 <- profiled
    gh_kernel<<<NOBJ, 256>>>(obj_dirs, gru_wh, gru_bh);                                // 4
    gru_kernel<<<BB*NOBJ, 128>>>(obj_dirs, gru_wi, gru_bi,
                                 mlp_w1, mlp_b1, mlp_w2, mlp_b2,
                                 norm_g, norm_b, slots_out);                           // 5
    for (int it=1; it<NITER; it++){
        attn_kernel<<<BB*16, 256>>>(radius_scale, attn_out);
        gru_kernel<<<BB*NOBJ, 128>>>(obj_dirs, gru_wi, gru_bi,
                                     mlp_w1, mlp_b1, mlp_w2, mlp_b2,
                                     norm_g, norm_b, slots_out);
    }
}

// round 15
// speedup vs baseline: 1.2854x; 1.0334x over previous
#include <cuda_runtime.h>
#include <cuda_bf16.h>
#include <math.h>

#define BB 16
#define NNP 2048
#define IND 64
#define HD 128
#define NOBJ 8
#define NSLOT 24
#define NITER 3

// ---------------- device scratch (static, no allocation) ----------------
__device__ float g_hyp[BB*NNP*HD];
__device__ float g_feats[BB*NNP*HD];
__device__ float g_x2[BB*NNP];
__device__ float g_f2[BB*NNP];
__device__ float g_fr[BB*NNP];
__device__ float g_density[BB*NNP];
__device__ float g_slots[BB*NSLOT*HD];
__device__ float g_s2[BB*NSLOT];
__device__ float g_sr[BB*NSLOT];
__device__ float g_gh[NOBJ*3*HD];
__device__ float g_upd[BB*NSLOT*HD];
__device__ float g_rowsum[BB*NSLOT];
__device__ __nv_bfloat162 g_xbf2[BB*NNP*IND/2];

__device__ __forceinline__ float geluf(float x){
    return 0.5f*x*(1.f+erff(x*0.70710678118654752f));
}
__device__ __forceinline__ float sigmoidf(float x){
    return 1.f/(1.f+expf(-x));
}

// ======================= encoder (resident weights, 512 threads / 16 warps) =======================
#define ENC_SMEM_FLOATS (IND*HD + HD*HD + HD*HD + 64*IND + 64*HD)   // 212,992 B

__global__ void __launch_bounds__(512) enc_kernel(const float* __restrict__ x,
    const float* __restrict__ fe_w1, const float* __restrict__ fe_b1,
    const float* __restrict__ ln1_g, const float* __restrict__ ln1_b,
    const float* __restrict__ fe_w2, const float* __restrict__ fe_b2,
    const float* __restrict__ ln2_g, const float* __restrict__ ln2_b,
    const float* __restrict__ hp_w,  const float* __restrict__ hp_b)
{
    extern __shared__ float sm[];
    float* s_w1 = sm;
    float* s_w2 = s_w1 + IND*HD;
    float* s_w3 = s_w2 + HD*HD;
    float* s_x  = s_w3 + HD*HD;
    float* s_h  = s_x  + 64*IND;

    const int tid = threadIdx.x;
    const int tokbase = blockIdx.x*64;
    {
        const float4* a=(const float4*)fe_w1; float4* d1=(float4*)s_w1;
        for (int i=tid;i<IND*HD/4;i+=512) d1[i]=a[i];
        const float4* b=(const float4*)fe_w2; float4* d2=(float4*)s_w2;
        for (int i=tid;i<HD*HD/4;i+=512) d2[i]=b[i];
        const float4* c=(const float4*)hp_w; float4* d3=(float4*)s_w3;
        for (int i=tid;i<HD*HD/4;i+=512) d3[i]=c[i];
        const float4* xs=(const float4*)(x + (size_t)tokbase*IND); float4* xd=(float4*)s_x;
        for (int i=tid;i<64*IND/4;i+=512) xd[i]=xs[i];
    }
    __syncthreads();
    if (tid < 64){
        float s=0.f;
        #pragma unroll 8
        for (int k=0;k<IND;k++){ float v=s_x[tid*IND+k]; s+=v*v; }
        g_x2[tokbase+tid]=s;
    }
    const int w = tid>>5, l = tid&31;   // 16 warps, each owns tokens w*4..w*4+3

    float acc[4][4];
    // ---- stage A: h1 = gelu(LN(x@W1+b1)) ----
    #pragma unroll
    for (int t=0;t<4;t++){acc[t][0]=acc[t][1]=acc[t][2]=acc[t][3]=0.f;}
    {
        const float4* w4=(const float4*)s_w1;
        for (int k=0;k<IND;k++){
            float4 wv = w4[k*32+l];
            #pragma unroll
            for (int t=0;t<4;t++){
                float xv = s_x[(w*4+t)*IND + k];
                acc[t][0]=fmaf(xv,wv.x,acc[t][0]); acc[t][1]=fmaf(xv,wv.y,acc[t][1]);
                acc[t][2]=fmaf(xv,wv.z,acc[t][2]); acc[t][3]=fmaf(xv,wv.w,acc[t][3]);
            }
        }
    }
    {
        float4 bv=((const float4*)fe_b1)[l];
        float4 gv=((const float4*)ln1_g)[l];
        float4 bt=((const float4*)ln1_b)[l];
        #pragma unroll
        for (int t=0;t<4;t++){
            float v0=acc[t][0]+bv.x, v1=acc[t][1]+bv.y, v2=acc[t][2]+bv.z, v3=acc[t][3]+bv.w;
            float s=v0+v1+v2+v3, q=v0*v0+v1*v1+v2*v2+v3*v3;
            #pragma unroll
            for (int o=16;o;o>>=1){ s+=__shfl_xor_sync(0xffffffffu,s,o); q+=__shfl_xor_sync(0xffffffffu,q,o); }
            float mu=s*(1.f/HD), var=q*(1.f/HD)-mu*mu;
            float inv=rsqrtf(var+1e-5f);
            v0=geluf((v0-mu)*inv*gv.x+bt.x); v1=geluf((v1-mu)*inv*gv.y+bt.y);
            v2=geluf((v2-mu)*inv*gv.z+bt.z); v3=geluf((v3-mu)*inv*gv.w+bt.w);
            float4* hv=(float4*)&s_h[(w*4+t)*HD + l*4];
            *hv = make_float4(v0,v1,v2,v3);
        }
    }
    __syncwarp();
    // ---- stage B: enc = LN(h1@W2+b2) ----
    #pragma unroll
    for (int t=0;t<4;t++){acc[t][0]=acc[t][1]=acc[t][2]=acc[t][3]=0.f;}
    {
        const float4* w4=(const float4*)s_w2;
        for (int k=0;k<HD;k++){
            float4 wv = w4[k*32+l];
            #pragma unroll
            for (int t=0;t<4;t++){
                float xv = s_h[(w*4+t)*HD + k];
                acc[t][0]=fmaf(xv,wv.x,acc[t][0]); acc[t][1]=fmaf(xv,wv.y,acc[t][1]);
                acc[t][2]=fmaf(xv,wv.z,acc[t][2]); acc[t][3]=fmaf(xv,wv.w,acc[t][3]);
            }
        }
    }
    {
        float4 bv=((const float4*)fe_b2)[l];
        float4 gv=((const float4*)ln2_g)[l];
        float4 bt=((const float4*)ln2_b)[l];
        #pragma unroll
        for (int t=0;t<4;t++){
            float v0=acc[t][0]+bv.x, v1=acc[t][1]+bv.y, v2=acc[t][2]+bv.z, v3=acc[t][3]+bv.w;
            float s=v0+v1+v2+v3, q=v0*v0+v1*v1+v2*v2+v3*v3;
            #pragma unroll
            for (int o=16;o;o>>=1){ s+=__shfl_xor_sync(0xffffffffu,s,o); q+=__shfl_xor_sync(0xffffffffu,q,o); }
            float mu=s*(1.f/HD), var=q*(1.f/HD)-mu*mu;
            float inv=rsqrtf(var+1e-5f);
            acc[t][0]=(v0-mu)*inv*gv.x+bt.x; acc[t][1]=(v1-mu)*inv*gv.y+bt.y;
            acc[t][2]=(v2-mu)*inv*gv.z+bt.z; acc[t][3]=(v3-mu)*inv*gv.w+bt.w;
        }
    }
    __syncwarp();
    #pragma unroll
    for (int t=0;t<4;t++){
        float4* hv=(float4*)&s_h[(w*4+t)*HD + l*4];
        *hv = make_float4(acc[t][0],acc[t][1],acc[t][2],acc[t][3]);
    }
    __syncwarp();
    // ---- stage C: hyp = tanh(enc@hp_w + hp_b) ----
    #pragma unroll
    for (int t=0;t<4;t++){acc[t][0]=acc[t][1]=acc[t][2]=acc[t][3]=0.f;}
    {
        const float4* w4=(const float4*)s_w3;
        for (int k=0;k<HD;k++){
            float4 wv = w4[k*32+l];
            #pragma unroll
            for (int t=0;t<4;t++){
                float xv = s_h[(w*4+t)*HD + k];
                acc[t][0]=fmaf(xv,wv.x,acc[t][0]); acc[t][1]=fmaf(xv,wv.y,acc[t][1]);
                acc[t][2]=fmaf(xv,wv.z,acc[t][2]); acc[t][3]=fmaf(xv,wv.w,acc[t][3]);
            }
        }
    }
    {
        float4 bv=((const float4*)hp_b)[l];
        #pragma unroll
        for (int t=0;t<4;t++){
            float4 hv;
            hv.x=tanhf(acc[t][0]+bv.x); hv.y=tanhf(acc[t][1]+bv.y);
            hv.z=tanhf(acc[t][2]+bv.z); hv.w=tanhf(acc[t][3]+bv.w);
            ((float4*)(g_hyp + (size_t)(tokbase + w*4 + t)*HD))[l]=hv;
        }
    }
}

// ======================= prep: xbf + zero scratch + slots init (merged) =======================
__global__ void prep_kernel(const float* __restrict__ x, const float* __restrict__ obj_dirs)
{
    const int bid = blockIdx.x, tid = threadIdx.x;
    int i = bid*256 + tid;
    float2 v = ((const float2*)x)[i];
    g_xbf2[i] = __float22bfloat162_rn(v);

    if (bid < 192){
        g_upd[bid*256 + tid] = 0.f;
    } else if (bid == 192){
        if (tid < BB*NSLOT) g_rowsum[tid] = 0.f;
    } else if (bid == 193){
        const int w=tid>>5, l=tid&31;
        if (w<NOBJ){
            float4 od=((const float4*)(obj_dirs + w*HD))[l];
            float q=od.x*od.x+od.y*od.y+od.z*od.z+od.w*od.w;
            #pragma unroll
            for (int o=16;o;o>>=1) q += __shfl_xor_sync(0xffffffffu,q,o);
            float nrm=sqrtf(q);
            float inv=1.f/fmaxf(nrm,1e-12f);
            float4 dn=make_float4(od.x*inv,od.y*inv,od.z*inv,od.w*inv);
            float qn=q*inv*inv;
            const float radii[3]={0.2f,0.5f,0.8f};
            for (int b=0;b<BB;b++){
                #pragma unroll
                for (int lv=0;lv<3;lv++){
                    float r=radii[lv];
                    ((float4*)(g_slots + (size_t)(b*NSLOT + w*3+lv)*HD))[l] =
                        make_float4(dn.x*r,dn.y*r,dn.z*r,dn.w*r);
                    if (l==0){
                        float s2=qn*r*r;
                        g_s2[b*NSLOT + w*3+lv]=s2;
                        g_sr[b*NSLOT + w*3+lv]=sqrtf(s2);
                    }
                }
            }
        }
    }
}

// ======================= density + feats (merged) =======================
__device__ __forceinline__ void ins6(float t[6], float v){
    if (v < t[5]){
        t[5]=v;
        #pragma unroll
        for (int s=5;s>0;s--){ if (t[s]<t[s-1]){ float tmp=t[s-1]; t[s-1]=t[s]; t[s]=tmp; } }
    }
}

#define JT_STRIDE 72

__global__ void __launch_bounds__(256) densfeats_kernel(float* __restrict__ dens_out)
{
    __shared__ float smf[3200];
    __nv_bfloat16* sxj = (__nv_bfloat16*)smf;
    float* x2s  = smf + (64*JT_STRIDE*2)/4;
    float* cand = smf;                         // [64][49] = 3136 floats
    float* s_dens = smf + 3136;                // [64]

    const int b  = blockIdx.y;
    const int i0 = blockIdx.x * 64;
    const int tid = threadIdx.x, w = tid>>5, lane = tid&31;
    const int g = lane>>2, tg = lane&3;
    const int rg = w & 3;
    const int jh = w >> 2;
    const int r0 = i0 + rg*16 + g;
    const unsigned short* xb = (const unsigned short*)g_xbf2 + (size_t)b*NNP*IND;

    unsigned int A[4][4];
    {
        const unsigned short* xr0 = xb + (size_t)r0*IND;
        const unsigned short* xr1 = xr0 + 8*IND;
        #pragma unroll
        for (int ks=0;ks<4;ks++){
            int kb = ks*16 + tg*2;
            A[ks][0] = *(const unsigned int*)&xr0[kb];
            A[ks][1] = *(const unsigned int*)&xr1[kb];
            A[ks][2] = *(const unsigned int*)&xr0[kb+8];
            A[ks][3] = *(const unsigned int*)&xr1[kb+8];
        }
    }
    float t6[2][6];
    #pragma unroll
    for (int r=0;r<2;r++){
        #pragma unroll
        for (int s=0;s<6;s++) t6[r][s]=1e30f;
    }

    for (int jt=0; jt<32; jt++){
        __syncthreads();
        {
            #pragma unroll
            for (int p=0;p<8;p++){
                int idx = tid + 256*p;
                int row = idx >> 5, c = idx & 31;
                unsigned int v = *(const unsigned int*)&xb[((size_t)(jt*64 + row))*IND + c*2];
                *(unsigned int*)&sxj[row*JT_STRIDE + c*2] = v;
            }
            if (tid < 64) x2s[tid] = g_x2[b*NNP + jt*64 + tid];
        }
        __syncthreads();
        #pragma unroll
        for (int q=0;q<4;q++){
            const int nt = jh*4 + q;
            const int n  = nt*8 + g;
            float c0=0.f,c1=0.f,c2=0.f,c3=0.f;
            #pragma unroll
            for (int ks=0;ks<4;ks++){
                const __nv_bfloat16* bp = &sxj[n*JT_STRIDE + ks*16 + tg*2];
                unsigned int B0 = *(const unsigned int*)bp;
                unsigned int B1 = *(const unsigned int*)(bp+8);
                asm("mma.sync.aligned.m16n8k16.row.col.f32.bf16.bf16.f32 "
                    "{%0,%1,%2,%3}, {%4,%5,%6,%7}, {%8,%9}, {%0,%1,%2,%3};"
                    : "+f"(c0),"+f"(c1),"+f"(c2),"+f"(c3)
                    : "r"(A[ks][0]),"r"(A[ks][1]),"r"(A[ks][2]),"r"(A[ks][3]),
                      "r"(B0),"r"(B1));
            }
            const int lc = nt*8 + tg*2;
            float xa = x2s[lc], xc = x2s[lc+1];
            ins6(t6[0], xa - 2.f*c0); ins6(t6[0], xc - 2.f*c1);
            ins6(t6[1], xa - 2.f*c2); ins6(t6[1], xc - 2.f*c3);
        }
    }
    __syncthreads();
    {
        int lr0 = rg*16 + g;
        int base = jh*24 + tg*6;
        #pragma unroll
        for (int s=0;s<6;s++){
            cand[lr0*49 + base + s]     = t6[0][s];
            cand[(lr0+8)*49 + base + s] = t6[1][s];
        }
    }
    __syncthreads();
    if (tid < 64){
        float u[6]={1e30f,1e30f,1e30f,1e30f,1e30f,1e30f};
        const float* row = &cand[tid*49];
        #pragma unroll 8
        for (int m=0;m<48;m++) ins6(u, row[m]);
        float x2i = g_x2[b*NNP + i0 + tid];
        float md = (sqrtf(fmaxf(x2i+u[1],0.f)) + sqrtf(fmaxf(x2i+u[2],0.f))
                  + sqrtf(fmaxf(x2i+u[3],0.f)) + sqrtf(fmaxf(x2i+u[4],0.f))
                  + sqrtf(fmaxf(x2i+u[5],0.f))) * 0.2f;
        float dv = tanhf(md);
        s_dens[tid] = dv;
        g_density[b*NNP + i0 + tid] = dv;
        dens_out [b*NNP + i0 + tid] = dv;
    }
    __syncthreads();
    // ---- feats phase ----
    #pragma unroll
    for (int t=0;t<8;t++){
        int row = w*8 + t;
        size_t n = (size_t)b*NNP + i0 + row;
        float4 v = ((const float4*)(g_hyp + n*HD))[lane];
        float q = v.x*v.x+v.y*v.y+v.z*v.z+v.w*v.w;
        #pragma unroll
        for (int o=16;o;o>>=1) q += __shfl_xor_sync(0xffffffffu,q,o);
        float fn = fmaxf(sqrtf(q),1e-6f);
        float dens = s_dens[row];
        float tr = (0.3f+0.5f*(1.f-dens))*0.95f;
        float sc = tr/fn;
        ((float4*)(g_feats + n*HD))[lane] = make_float4(v.x*sc,v.y*sc,v.z*sc,v.w*sc);
        if (lane==0){
            float f2=q*sc*sc;
            g_f2[n]=f2; g_fr[n]=sqrtf(f2);
        }
    }
}

// ======================= gh precompute =======================
__global__ void gh_kernel(const float* __restrict__ obj_dirs,
                          const float* __restrict__ gru_wh,
                          const float* __restrict__ gru_bh)
{
    const int o = blockIdx.x;
    const int w = threadIdx.x>>5, l = threadIdx.x&31;
    float4 od = ((const float4*)(obj_dirs + (size_t)o*HD))[l];
    for (int m=0;m<48;m++){
        int r = w*48 + m;
        float4 wv = ((const float4*)(gru_wh + (size_t)r*HD))[l];
        float p = od.x*wv.x + od.y*wv.y + od.z*wv.z + od.w*wv.w;
        #pragma unroll
        for (int of=16;of;of>>=1) p += __shfl_xor_sync(0xffffffffu,p,of);
        if (l==0) g_gh[o*3*HD + r] = p + gru_bh[r];
    }
}

// ======================= attention: two-phase chunked, 2 blocks/SM (R14 version) =======================
#define FPAD 132
#define APAD 25
__global__ void __launch_bounds__(256,2) attn_kernel(const float* __restrict__ rs_ptr,
                                                     float* __restrict__ attn_out)
{
    __shared__ float s_slots[NSLOT*HD];        // 12288 B
    __shared__ float s_feats[32*FPAD];         // 16896 B
    __shared__ float s_attn[32*APAD];          // 3200 B
    __shared__ float s_f2[32], s_fr[32], s_dn[32];
    __shared__ float s_s2[NSLOT], s_sr[NSLOT];
    const int b = blockIdx.x >> 4;
    const int nbase = (blockIdx.x & 15) * 128;
    const int tid=threadIdx.x, w=tid>>5, l=tid&31;
    {
        const float4* ss=(const float4*)(g_slots + (size_t)b*NSLOT*HD);
        float4* sd=(float4*)s_slots;
        for (int i=tid;i<NSLOT*HD/4;i+=256) sd[i]=ss[i];
        if (tid<NSLOT){ s_s2[tid]=g_s2[b*NSLOT+tid]; s_sr[tid]=g_sr[b*NSLOT+tid]; }
    }
    const float rs = *rs_ptr;
    float4 acc0=make_float4(0.f,0.f,0.f,0.f);
    float4 acc1=make_float4(0.f,0.f,0.f,0.f);
    float4 acc2=make_float4(0.f,0.f,0.f,0.f);
    float rsum=0.f;
    const int lvl = (l<NSLOT)? (l - (l/3)*3) : 0;
    const float basel = (lvl==0)?2.f:((lvl==1)?1.f:0.5f);
    const float4* slots4=(const float4*)s_slots;

    for (int ch=0; ch<4; ch++){
        __syncthreads();
        {   // stage 32 tokens of feats + stats
            const int n0 = nbase + ch*32;
            #pragma unroll
            for (int p=0;p<4;p++){
                int i = tid + 256*p;               // 1024 float4
                int row = i>>5, c = i&31;
                ((float4*)&s_feats[row*FPAD])[c] =
                    ((const float4*)(g_feats + ((size_t)b*NNP + n0 + row)*HD))[c];
            }
            if (tid<32){
                size_t off=(size_t)b*NNP + n0 + tid;
                s_f2[tid]=g_f2[off]; s_fr[tid]=g_fr[off]; s_dn[tid]=g_density[off];
            }
        }
        __syncthreads();
        // ---- phase 1 ----
        const float s2k = (l<NSLOT)? s_s2[l] : 0.f;
        const float srk = (l<NSLOT)? s_sr[l] : 0.f;
        #pragma unroll 1
        for (int ii=0;ii<4;ii++){
            const int row = w*4 + ii;
            float4 f = ((const float4*)&s_feats[row*FPAD])[l];
            float f2n=s_f2[row], frn=s_fr[row], dens=s_dn[row];
            float mod = rs*(dens-0.5f);
            float mydot=0.f;
            #pragma unroll
            for (int k=0;k<NSLOT;k++){
                float4 sv=slots4[k*32+l];
                float p = f.x*sv.x+f.y*sv.y+f.z*sv.z+f.w*sv.w;
                p += __shfl_xor_sync(0xffffffffu,p,16);
                p += __shfl_xor_sync(0xffffffffu,p,8);
                p += __shfl_xor_sync(0xffffffffu,p,4);
                p += __shfl_xor_sync(0xffffffffu,p,2);
                p += __shfl_xor_sync(0xffffffffu,p,1);
                if (l==k) mydot=p;
            }
            float logit=-1e30f;
            if (l<NSLOT){
                float diff2 = fmaxf(f2n + s2k - 2.f*mydot, 0.f);
                float xn = fminf(f2n, 1.f-1e-5f);
                float yn = fminf(s2k, 1.f-1e-5f);
                float den = fmaxf((1.f-xn)*(1.f-yn), 1e-6f);
                float arg = fmaxf(1.f + 2.f*diff2/den, 1.f+1e-6f);
                float hd = acoshf(arg);
                float rd = fabsf(frn-srk);
                float scv = fminf(fmaxf(basel+mod,0.3f),3.f);
                logit = (-hd - 3.f*rd)*scv*10.f;   // /TAU
            }
            float m=logit;
            #pragma unroll
            for (int o=16;o;o>>=1) m=fmaxf(m,__shfl_xor_sync(0xffffffffu,m,o));
            float e=(l<NSLOT)? expf(logit-m):0.f;
            float s=e;
            #pragma unroll
            for (int o=16;o;o>>=1) s+=__shfl_xor_sync(0xffffffffu,s,o);
            float a=e/s;
            if (l<NSLOT){
                s_attn[row*APAD + l]=a;
                rsum += a;
            }
        }
        __syncthreads();
        // ---- phase 2a: coalesced attn_out stores ----
        if (tid < 192){
            int k = tid>>3, q = tid&7;
            float4 v;
            v.x = s_attn[(q*4+0)*APAD + k];
            v.y = s_attn[(q*4+1)*APAD + k];
            v.z = s_attn[(q*4+2)*APAD + k];
            v.w = s_attn[(q*4+3)*APAD + k];
            *(float4*)&attn_out[((size_t)b*NSLOT+k)*NNP + nbase + ch*32 + q*4] = v;
        }
        // ---- phase 2b: upd mini-GEMM ----
        #pragma unroll
        for (int p=0;p<3;p++){
            int idx = p*256 + tid;
            int k = idx>>5, h4 = idx&31;
            float4 a4 = (p==0)?acc0:((p==1)?acc1:acc2);
            #pragma unroll 8
            for (int n=0;n<32;n++){
                float av = s_attn[n*APAD + k];
                float4 fv = ((const float4*)&s_feats[n*FPAD])[h4];
                a4.x=fmaf(av,fv.x,a4.x); a4.y=fmaf(av,fv.y,a4.y);
                a4.z=fmaf(av,fv.z,a4.z); a4.w=fmaf(av,fv.w,a4.w);
            }
            if (p==0) acc0=a4; else if (p==1) acc1=a4; else acc2=a4;
        }
    }
    // ---- finalize ----
    if (l<NSLOT) atomicAdd(&g_rowsum[b*NSLOT+l], rsum);
    #pragma unroll
    for (int p=0;p<3;p++){
        int idx = p*256 + tid;
        int k = idx>>5, h4 = idx&31;
        float4 a4 = (p==0)?acc0:((p==1)?acc1:acc2);
        float* up = g_upd + ((size_t)b*NSLOT+k)*HD + h4*4;
        atomicAdd(up+0,a4.x); atomicAdd(up+1,a4.y);
        atomicAdd(up+2,a4.z); atomicAdd(up+3,a4.w);
    }
}

// ======================= GRU + MLP + renorm (warp-row gi, coalesced) =======================
__device__ __forceinline__ float blksum128(float v, volatile float* red){
    #pragma unroll
    for (int o=16;o;o>>=1) v += __shfl_xor_sync(0xffffffffu,v,o);
    __syncthreads();
    if ((threadIdx.x&31)==0) red[threadIdx.x>>5]=v;
    __syncthreads();
    return red[0]+red[1]+red[2]+red[3];
}

__global__ void __launch_bounds__(128) gru_kernel(const float* __restrict__ obj_dirs,
    const float* __restrict__ gru_wi, const float* __restrict__ gru_bi,
    const float* __restrict__ mlp_w1, const float* __restrict__ mlp_b1,
    const float* __restrict__ mlp_w2, const float* __restrict__ mlp_b2,
    const float* __restrict__ norm_g, const float* __restrict__ norm_b,
    float* __restrict__ slots_out)
{
    __shared__ float s_buf[HD];
    __shared__ float s_gi[3*HD];
    __shared__ float s_red[4];
    const int b = blockIdx.x >> 3, o = blockIdx.x & 7;
    const int h = threadIdx.x, w = h>>5, l = h&31;
    float ou=0.f;
    #pragma unroll
    for (int lv=0;lv<3;lv++){
        int k=o*3+lv;
        ou += g_upd[((size_t)b*NSLOT+k)*HD + h] / (g_rowsum[b*NSLOT+k]+1e-8f);
    }
    s_buf[h]=ou; __syncthreads();
    #pragma unroll
    for (int lv=0;lv<3;lv++){
        int k=o*3+lv;
        g_upd[((size_t)b*NSLOT+k)*HD + h]=0.f;
        if (h==lv) g_rowsum[b*NSLOT+k]=0.f;
    }
    {
        float4 ob = ((const float4*)s_buf)[l];
        for (int m=0;m<96;m++){
            int r = w*96 + m;
            float4 wv = ((const float4*)(gru_wi + (size_t)r*HD))[l];
            float p = ob.x*wv.x + ob.y*wv.y + ob.z*wv.z + ob.w*wv.w;
            #pragma unroll
            for (int of=16;of;of>>=1) p += __shfl_xor_sync(0xffffffffu,p,of);
            if (l==0) s_gi[r] = p + gru_bi[r];
        }
    }
    __syncthreads();
    float hr=g_gh[o*3*HD + h], hz=g_gh[o*3*HD + HD + h], hn=g_gh[o*3*HD + 2*HD + h];
    float rr=sigmoidf(s_gi[h]+hr);
    float z =sigmoidf(s_gi[HD+h]+hz);
    float nnv=tanhf(s_gi[2*HD+h]+rr*hn);
    float oldh=obj_dirs[o*HD+h];
    float nd=(1.f-z)*nnv + z*oldh;
    float s = blksum128(nd, s_red);
    float q = blksum128(nd*nd, s_red);
    float mu=s*(1.f/HD), var=q*(1.f/HD)-mu*mu;
    float ln=(nd-mu)*rsqrtf(var+1e-5f)*norm_g[h]+norm_b[h];
    __syncthreads(); s_buf[h]=ln; __syncthreads();
    float m1=mlp_b1[h];
    {
        const float* w1=mlp_w1;
        #pragma unroll 8
        for (int hh=0;hh<HD;hh++) m1=fmaf(s_buf[hh],w1[(size_t)hh*HD+h],m1);
    }
    m1=geluf(m1);
    __syncthreads(); s_buf[h]=m1; __syncthreads();
    float m2=mlp_b2[h];
    {
        const float* w2=mlp_w2;
        #pragma unroll 8
        for (int hh=0;hh<HD;hh++) m2=fmaf(s_buf[hh],w2[(size_t)hh*HD+h],m2);
    }
    float nd2 = nd + 0.2f*m2;
    float q2 = blksum128(nd2*nd2, s_red);
    float nrm = fmaxf(sqrtf(q2),1e-12f);
    float ndn = nd2/nrm;
    float qn = q2/(nrm*nrm);
    const float radii[3]={0.2f,0.5f,0.8f};
    #pragma unroll
    for (int lv=0;lv<3;lv++){
        float r=radii[lv];
        float v=ndn*r;
        size_t idx=((size_t)b*NSLOT + o*3+lv)*HD + h;
        g_slots[idx]=v;
        slots_out[idx]=v;
    }
    if (h<3){
        float r=radii[h];
        float s2v=qn*r*r;
        g_s2[b*NSLOT + o*3 + h]=s2v;
        g_sr[b*NSLOT + o*3 + h]=sqrtf(s2v);
    }
}

// ======================= host launch =======================
extern "C" void kernel_launch(void* const* d_in, const int* in_sizes, int n_in,
                              void* d_out, int out_size)
{
    const float* x      = (const float*)d_in[0];
    const float* fe_w1  = (const float*)d_in[1];
    const float* fe_b1  = (const float*)d_in[2];
    const float* ln1_g  = (const float*)d_in[3];
    const float* ln1_b  = (const float*)d_in[4];
    const float* fe_w2  = (const float*)d_in[5];
    const float* fe_b2  = (const float*)d_in[6];
    const float* ln2_g  = (const float*)d_in[7];
    const float* ln2_b  = (const float*)d_in[8];
    const float* hp_w   = (const float*)d_in[9];
    const float* hp_b   = (const float*)d_in[10];
    const float* obj_dirs = (const float*)d_in[11];
    const float* radius_scale = (const float*)d_in[12];
    const float* gru_wi = (const float*)d_in[13];
    const float* gru_wh = (const float*)d_in[14];
    const float* gru_bi = (const float*)d_in[15];
    const float* gru_bh = (const float*)d_in[16];
    const float* mlp_w1 = (const float*)d_in[17];
    const float* mlp_b1 = (const float*)d_in[18];
    const float* mlp_w2 = (const float*)d_in[19];
    const float* mlp_b2 = (const float*)d_in[20];
    const float* norm_g = (const float*)d_in[21];
    const float* norm_b = (const float*)d_in[22];

    float* out = (float*)d_out;
    float* slots_out = out;                                   // [16,24,128]
    float* attn_out  = out + BB*NSLOT*HD;                     // [16,24,2048]
    float* dens_out  = attn_out + (size_t)BB*NSLOT*NNP;       // [16,2048]

    size_t encSmem = (size_t)ENC_SMEM_FLOATS*sizeof(float);   // 212,992 B
    cudaFuncSetAttribute(enc_kernel, cudaFuncAttributeMaxDynamicSharedMemorySize, (int)encSmem);

    // Launch order: attn_kernel is the 0-based 4th launch (ncu capture point).
    enc_kernel<<<BB*NNP/64, 512, encSmem>>>(x, fe_w1, fe_b1, ln1_g, ln1_b,
                                            fe_w2, fe_b2, ln2_g, ln2_b, hp_w, hp_b);   // 0
    prep_kernel<<<BB*NNP*IND/2/256, 256>>>(x, obj_dirs);                               // 1
    {
        dim3 g(NNP/64, BB);
        densfeats_kernel<<<g, 256>>>(dens_out);                                        // 2
    }
    attn_kernel<<<BB*16, 256>>>(radius_scale, attn_out);                               // 3 <- profiled
    gh_kernel<<<NOBJ, 256>>>(obj_dirs, gru_wh, gru_bh);                                // 4
    gru_kernel<<<BB*NOBJ, 128>>>(obj_dirs, gru_wi, gru_bi,
                                 mlp_w1, mlp_b1, mlp_w2, mlp_b2,
                                 norm_g, norm_b, slots_out);                           // 5
    for (int it=1; it<NITER; it++){
        attn_kernel<<<BB*16, 256>>>(radius_scale, attn_out);
        gru_kernel<<<BB*NOBJ, 128>>>(obj_dirs, gru_wi, gru_bi,
                                     mlp_w1, mlp_b1, mlp_w2, mlp_b2,
                                     norm_g, norm_b, slots_out);
    }
}

// round 16
// speedup vs baseline: 1.4113x; 1.0979x over previous
#include <cuda_runtime.h>
#include <cuda_bf16.h>
#include <math.h>

#define BB 16
#define NNP 2048
#define IND 64
#define HD 128
#define NOBJ 8
#define NSLOT 24
#define NITER 3

// ---------------- device scratch (static, no allocation) ----------------
__device__ float g_hyp[BB*NNP*HD];
__device__ float g_feats[BB*NNP*HD];
__device__ float g_x2[BB*NNP];
__device__ float g_f2[BB*NNP];
__device__ float g_fr[BB*NNP];
__device__ float g_density[BB*NNP];
__device__ float g_slots[BB*NSLOT*HD];
__device__ float g_s2[BB*NSLOT];
__device__ float g_sr[BB*NSLOT];
__device__ float g_gh[NOBJ*3*HD];
__device__ float g_upd[BB*NSLOT*HD];
__device__ float g_rowsum[BB*NSLOT];
__device__ __nv_bfloat162 g_xbf2[BB*NNP*IND/2];

__device__ __forceinline__ float geluf(float x){
    return 0.5f*x*(1.f+erff(x*0.70710678118654752f));
}
__device__ __forceinline__ float sigmoidf(float x){
    return 1.f/(1.f+expf(-x));
}

// ======================= encoder (resident weights, 512 threads / 16 warps) =======================
#define ENC_SMEM_FLOATS (IND*HD + HD*HD + HD*HD + 64*IND + 64*HD)   // 212,992 B

__global__ void __launch_bounds__(512) enc_kernel(const float* __restrict__ x,
    const float* __restrict__ fe_w1, const float* __restrict__ fe_b1,
    const float* __restrict__ ln1_g, const float* __restrict__ ln1_b,
    const float* __restrict__ fe_w2, const float* __restrict__ fe_b2,
    const float* __restrict__ ln2_g, const float* __restrict__ ln2_b,
    const float* __restrict__ hp_w,  const float* __restrict__ hp_b)
{
    extern __shared__ float sm[];
    float* s_w1 = sm;
    float* s_w2 = s_w1 + IND*HD;
    float* s_w3 = s_w2 + HD*HD;
    float* s_x  = s_w3 + HD*HD;
    float* s_h  = s_x  + 64*IND;

    const int tid = threadIdx.x;
    const int tokbase = blockIdx.x*64;
    {
        const float4* a=(const float4*)fe_w1; float4* d1=(float4*)s_w1;
        for (int i=tid;i<IND*HD/4;i+=512) d1[i]=a[i];
        const float4* b=(const float4*)fe_w2; float4* d2=(float4*)s_w2;
        for (int i=tid;i<HD*HD/4;i+=512) d2[i]=b[i];
        const float4* c=(const float4*)hp_w; float4* d3=(float4*)s_w3;
        for (int i=tid;i<HD*HD/4;i+=512) d3[i]=c[i];
        const float4* xs=(const float4*)(x + (size_t)tokbase*IND); float4* xd=(float4*)s_x;
        for (int i=tid;i<64*IND/4;i+=512) xd[i]=xs[i];
    }
    __syncthreads();
    if (tid < 64){
        float s=0.f;
        #pragma unroll 8
        for (int k=0;k<IND;k++){ float v=s_x[tid*IND+k]; s+=v*v; }
        g_x2[tokbase+tid]=s;
    }
    const int w = tid>>5, l = tid&31;   // 16 warps, each owns tokens w*4..w*4+3

    float acc[4][4];
    #pragma unroll
    for (int t=0;t<4;t++){acc[t][0]=acc[t][1]=acc[t][2]=acc[t][3]=0.f;}
    {
        const float4* w4=(const float4*)s_w1;
        for (int k=0;k<IND;k++){
            float4 wv = w4[k*32+l];
            #pragma unroll
            for (int t=0;t<4;t++){
                float xv = s_x[(w*4+t)*IND + k];
                acc[t][0]=fmaf(xv,wv.x,acc[t][0]); acc[t][1]=fmaf(xv,wv.y,acc[t][1]);
                acc[t][2]=fmaf(xv,wv.z,acc[t][2]); acc[t][3]=fmaf(xv,wv.w,acc[t][3]);
            }
        }
    }
    {
        float4 bv=((const float4*)fe_b1)[l];
        float4 gv=((const float4*)ln1_g)[l];
        float4 bt=((const float4*)ln1_b)[l];
        #pragma unroll
        for (int t=0;t<4;t++){
            float v0=acc[t][0]+bv.x, v1=acc[t][1]+bv.y, v2=acc[t][2]+bv.z, v3=acc[t][3]+bv.w;
            float s=v0+v1+v2+v3, q=v0*v0+v1*v1+v2*v2+v3*v3;
            #pragma unroll
            for (int o=16;o;o>>=1){ s+=__shfl_xor_sync(0xffffffffu,s,o); q+=__shfl_xor_sync(0xffffffffu,q,o); }
            float mu=s*(1.f/HD), var=q*(1.f/HD)-mu*mu;
            float inv=rsqrtf(var+1e-5f);
            v0=geluf((v0-mu)*inv*gv.x+bt.x); v1=geluf((v1-mu)*inv*gv.y+bt.y);
            v2=geluf((v2-mu)*inv*gv.z+bt.z); v3=geluf((v3-mu)*inv*gv.w+bt.w);
            float4* hv=(float4*)&s_h[(w*4+t)*HD + l*4];
            *hv = make_float4(v0,v1,v2,v3);
        }
    }
    __syncwarp();
    #pragma unroll
    for (int t=0;t<4;t++){acc[t][0]=acc[t][1]=acc[t][2]=acc[t][3]=0.f;}
    {
        const float4* w4=(const float4*)s_w2;
        for (int k=0;k<HD;k++){
            float4 wv = w4[k*32+l];
            #pragma unroll
            for (int t=0;t<4;t++){
                float xv = s_h[(w*4+t)*HD + k];
                acc[t][0]=fmaf(xv,wv.x,acc[t][0]); acc[t][1]=fmaf(xv,wv.y,acc[t][1]);
                acc[t][2]=fmaf(xv,wv.z,acc[t][2]); acc[t][3]=fmaf(xv,wv.w,acc[t][3]);
            }
        }
    }
    {
        float4 bv=((const float4*)fe_b2)[l];
        float4 gv=((const float4*)ln2_g)[l];
        float4 bt=((const float4*)ln2_b)[l];
        #pragma unroll
        for (int t=0;t<4;t++){
            float v0=acc[t][0]+bv.x, v1=acc[t][1]+bv.y, v2=acc[t][2]+bv.z, v3=acc[t][3]+bv.w;
            float s=v0+v1+v2+v3, q=v0*v0+v1*v1+v2*v2+v3*v3;
            #pragma unroll
            for (int o=16;o;o>>=1){ s+=__shfl_xor_sync(0xffffffffu,s,o); q+=__shfl_xor_sync(0xffffffffu,q,o); }
            float mu=s*(1.f/HD), var=q*(1.f/HD)-mu*mu;
            float inv=rsqrtf(var+1e-5f);
            acc[t][0]=(v0-mu)*inv*gv.x+bt.x; acc[t][1]=(v1-mu)*inv*gv.y+bt.y;
            acc[t][2]=(v2-mu)*inv*gv.z+bt.z; acc[t][3]=(v3-mu)*inv*gv.w+bt.w;
        }
    }
    __syncwarp();
    #pragma unroll
    for (int t=0;t<4;t++){
        float4* hv=(float4*)&s_h[(w*4+t)*HD + l*4];
        *hv = make_float4(acc[t][0],acc[t][1],acc[t][2],acc[t][3]);
    }
    __syncwarp();
    #pragma unroll
    for (int t=0;t<4;t++){acc[t][0]=acc[t][1]=acc[t][2]=acc[t][3]=0.f;}
    {
        const float4* w4=(const float4*)s_w3;
        for (int k=0;k<HD;k++){
            float4 wv = w4[k*32+l];
            #pragma unroll
            for (int t=0;t<4;t++){
                float xv = s_h[(w*4+t)*HD + k];
                acc[t][0]=fmaf(xv,wv.x,acc[t][0]); acc[t][1]=fmaf(xv,wv.y,acc[t][1]);
                acc[t][2]=fmaf(xv,wv.z,acc[t][2]); acc[t][3]=fmaf(xv,wv.w,acc[t][3]);
            }
        }
    }
    {
        float4 bv=((const float4*)hp_b)[l];
        #pragma unroll
        for (int t=0;t<4;t++){
            float4 hv;
            hv.x=tanhf(acc[t][0]+bv.x); hv.y=tanhf(acc[t][1]+bv.y);
            hv.z=tanhf(acc[t][2]+bv.z); hv.w=tanhf(acc[t][3]+bv.w);
            ((float4*)(g_hyp + (size_t)(tokbase + w*4 + t)*HD))[l]=hv;
        }
    }
}

// ======================= prep: xbf + zero scratch + slots init (merged) =======================
__global__ void prep_kernel(const float* __restrict__ x, const float* __restrict__ obj_dirs)
{
    const int bid = blockIdx.x, tid = threadIdx.x;
    int i = bid*256 + tid;
    float2 v = ((const float2*)x)[i];
    g_xbf2[i] = __float22bfloat162_rn(v);

    if (bid < 192){
        g_upd[bid*256 + tid] = 0.f;
    } else if (bid == 192){
        if (tid < BB*NSLOT) g_rowsum[tid] = 0.f;
    } else if (bid == 193){
        const int w=tid>>5, l=tid&31;
        if (w<NOBJ){
            float4 od=((const float4*)(obj_dirs + w*HD))[l];
            float q=od.x*od.x+od.y*od.y+od.z*od.z+od.w*od.w;
            #pragma unroll
            for (int o=16;o;o>>=1) q += __shfl_xor_sync(0xffffffffu,q,o);
            float nrm=sqrtf(q);
            float inv=1.f/fmaxf(nrm,1e-12f);
            float4 dn=make_float4(od.x*inv,od.y*inv,od.z*inv,od.w*inv);
            float qn=q*inv*inv;
            const float radii[3]={0.2f,0.5f,0.8f};
            for (int b=0;b<BB;b++){
                #pragma unroll
                for (int lv=0;lv<3;lv++){
                    float r=radii[lv];
                    ((float4*)(g_slots + (size_t)(b*NSLOT + w*3+lv)*HD))[l] =
                        make_float4(dn.x*r,dn.y*r,dn.z*r,dn.w*r);
                    if (l==0){
                        float s2=qn*r*r;
                        g_s2[b*NSLOT + w*3+lv]=s2;
                        g_sr[b*NSLOT + w*3+lv]=sqrtf(s2);
                    }
                }
            }
        }
    }
}

// ======================= density + feats (merged) =======================
__device__ __forceinline__ void ins6(float t[6], float v){
    if (v < t[5]){
        t[5]=v;
        #pragma unroll
        for (int s=5;s>0;s--){ if (t[s]<t[s-1]){ float tmp=t[s-1]; t[s-1]=t[s]; t[s]=tmp; } }
    }
}

#define JT_STRIDE 72

__global__ void __launch_bounds__(256) densfeats_kernel(float* __restrict__ dens_out)
{
    __shared__ float smf[3200];
    __nv_bfloat16* sxj = (__nv_bfloat16*)smf;
    float* x2s  = smf + (64*JT_STRIDE*2)/4;
    float* cand = smf;                         // [64][49] = 3136 floats
    float* s_dens = smf + 3136;                // [64]

    const int b  = blockIdx.y;
    const int i0 = blockIdx.x * 64;
    const int tid = threadIdx.x, w = tid>>5, lane = tid&31;
    const int g = lane>>2, tg = lane&3;
    const int rg = w & 3;
    const int jh = w >> 2;
    const int r0 = i0 + rg*16 + g;
    const unsigned short* xb = (const unsigned short*)g_xbf2 + (size_t)b*NNP*IND;

    unsigned int A[4][4];
    {
        const unsigned short* xr0 = xb + (size_t)r0*IND;
        const unsigned short* xr1 = xr0 + 8*IND;
        #pragma unroll
        for (int ks=0;ks<4;ks++){
            int kb = ks*16 + tg*2;
            A[ks][0] = *(const unsigned int*)&xr0[kb];
            A[ks][1] = *(const unsigned int*)&xr1[kb];
            A[ks][2] = *(const unsigned int*)&xr0[kb+8];
            A[ks][3] = *(const unsigned int*)&xr1[kb+8];
        }
    }
    float t6[2][6];
    #pragma unroll
    for (int r=0;r<2;r++){
        #pragma unroll
        for (int s=0;s<6;s++) t6[r][s]=1e30f;
    }

    for (int jt=0; jt<32; jt++){
        __syncthreads();
        {
            #pragma unroll
            for (int p=0;p<8;p++){
                int idx = tid + 256*p;
                int row = idx >> 5, c = idx & 31;
                unsigned int v = *(const unsigned int*)&xb[((size_t)(jt*64 + row))*IND + c*2];
                *(unsigned int*)&sxj[row*JT_STRIDE + c*2] = v;
            }
            if (tid < 64) x2s[tid] = g_x2[b*NNP + jt*64 + tid];
        }
        __syncthreads();
        #pragma unroll
        for (int q=0;q<4;q++){
            const int nt = jh*4 + q;
            const int n  = nt*8 + g;
            float c0=0.f,c1=0.f,c2=0.f,c3=0.f;
            #pragma unroll
            for (int ks=0;ks<4;ks++){
                const __nv_bfloat16* bp = &sxj[n*JT_STRIDE + ks*16 + tg*2];
                unsigned int B0 = *(const unsigned int*)bp;
                unsigned int B1 = *(const unsigned int*)(bp+8);
                asm("mma.sync.aligned.m16n8k16.row.col.f32.bf16.bf16.f32 "
                    "{%0,%1,%2,%3}, {%4,%5,%6,%7}, {%8,%9}, {%0,%1,%2,%3};"
                    : "+f"(c0),"+f"(c1),"+f"(c2),"+f"(c3)
                    : "r"(A[ks][0]),"r"(A[ks][1]),"r"(A[ks][2]),"r"(A[ks][3]),
                      "r"(B0),"r"(B1));
            }
            const int lc = nt*8 + tg*2;
            float xa = x2s[lc], xc = x2s[lc+1];
            ins6(t6[0], xa - 2.f*c0); ins6(t6[0], xc - 2.f*c1);
            ins6(t6[1], xa - 2.f*c2); ins6(t6[1], xc - 2.f*c3);
        }
    }
    __syncthreads();
    {
        int lr0 = rg*16 + g;
        int base = jh*24 + tg*6;
        #pragma unroll
        for (int s=0;s<6;s++){
            cand[lr0*49 + base + s]     = t6[0][s];
            cand[(lr0+8)*49 + base + s] = t6[1][s];
        }
    }
    __syncthreads();
    if (tid < 64){
        float u[6]={1e30f,1e30f,1e30f,1e30f,1e30f,1e30f};
        const float* row = &cand[tid*49];
        #pragma unroll 8
        for (int m=0;m<48;m++) ins6(u, row[m]);
        float x2i = g_x2[b*NNP + i0 + tid];
        float md = (sqrtf(fmaxf(x2i+u[1],0.f)) + sqrtf(fmaxf(x2i+u[2],0.f))
                  + sqrtf(fmaxf(x2i+u[3],0.f)) + sqrtf(fmaxf(x2i+u[4],0.f))
                  + sqrtf(fmaxf(x2i+u[5],0.f))) * 0.2f;
        float dv = tanhf(md);
        s_dens[tid] = dv;
        g_density[b*NNP + i0 + tid] = dv;
        dens_out [b*NNP + i0 + tid] = dv;
    }
    __syncthreads();
    // ---- feats phase ----
    #pragma unroll
    for (int t=0;t<8;t++){
        int row = w*8 + t;
        size_t n = (size_t)b*NNP + i0 + row;
        float4 v = ((const float4*)(g_hyp + n*HD))[lane];
        float q = v.x*v.x+v.y*v.y+v.z*v.z+v.w*v.w;
        #pragma unroll
        for (int o=16;o;o>>=1) q += __shfl_xor_sync(0xffffffffu,q,o);
        float fn = fmaxf(sqrtf(q),1e-6f);
        float dens = s_dens[row];
        float tr = (0.3f+0.5f*(1.f-dens))*0.95f;
        float sc = tr/fn;
        ((float4*)(g_feats + n*HD))[lane] = make_float4(v.x*sc,v.y*sc,v.z*sc,v.w*sc);
        if (lane==0){
            float f2=q*sc*sc;
            g_f2[n]=f2; g_fr[n]=sqrtf(f2);
        }
    }
}

// ======================= gh precompute =======================
__global__ void gh_kernel(const float* __restrict__ obj_dirs,
                          const float* __restrict__ gru_wh,
                          const float* __restrict__ gru_bh)
{
    const int o = blockIdx.x;
    const int w = threadIdx.x>>5, l = threadIdx.x&31;
    float4 od = ((const float4*)(obj_dirs + (size_t)o*HD))[l];
    for (int m=0;m<48;m++){
        int r = w*48 + m;
        float4 wv = ((const float4*)(gru_wh + (size_t)r*HD))[l];
        float p = od.x*wv.x + od.y*wv.y + od.z*wv.z + od.w*wv.w;
        #pragma unroll
        for (int of=16;of;of>>=1) p += __shfl_xor_sync(0xffffffffu,p,of);
        if (l==0) g_gh[o*3*HD + r] = p + gru_bh[r];
    }
}

// ======================= attention: shuffle-free phase 1, 2 blocks/SM =======================
#define FPAD 132
#define APAD 25
__global__ void __launch_bounds__(256,2) attn_kernel(const float* __restrict__ rs_ptr,
                                                     float* __restrict__ attn_out)
{
    __shared__ float s_slots[NSLOT*FPAD];      // padded: conflict-free (slot,c) reads
    __shared__ float s_feats[32*FPAD];
    __shared__ float s_attn[32*APAD];
    __shared__ float s_f2[32], s_fr[32], s_dn[32];
    __shared__ float s_s2[NSLOT], s_sr[NSLOT];
    const int b = blockIdx.x >> 4;
    const int nbase = (blockIdx.x & 15) * 128;
    const int tid=threadIdx.x;
    {
        const float* gs = g_slots + (size_t)b*NSLOT*HD;
        for (int i=tid;i<NSLOT*32;i+=256){           // 768 float4
            int row=i>>5, c=i&31;
            ((float4*)&s_slots[row*FPAD])[c] = ((const float4*)(gs + row*HD))[c];
        }
        if (tid<NSLOT){ s_s2[tid]=g_s2[b*NSLOT+tid]; s_sr[tid]=g_sr[b*NSLOT+tid]; }
    }
    const float rs = *rs_ptr;
    float4 acc0=make_float4(0.f,0.f,0.f,0.f);
    float4 acc1=make_float4(0.f,0.f,0.f,0.f);
    float4 acc2=make_float4(0.f,0.f,0.f,0.f);
    float rsum=0.f;

    for (int ch=0; ch<4; ch++){
        __syncthreads();
        {   // stage 32 tokens of feats + stats
            const int n0 = nbase + ch*32;
            #pragma unroll
            for (int p=0;p<4;p++){
                int i = tid + 256*p;               // 1024 float4
                int row = i>>5, c = i&31;
                ((float4*)&s_feats[row*FPAD])[c] =
                    ((const float4*)(g_feats + ((size_t)b*NNP + n0 + row)*HD))[c];
            }
            if (tid<32){
                size_t off=(size_t)b*NNP + n0 + tid;
                s_f2[tid]=g_f2[off]; s_fr[tid]=g_fr[off]; s_dn[tid]=g_density[off];
            }
        }
        __syncthreads();
        // ---- phase 1: 768 independent (token,slot) dots, no shuffles ----
        #pragma unroll
        for (int p=0;p<3;p++){
            int idx = p*256 + tid;                 // < 768
            int token = idx/24, slot = idx - token*24;
            const float4* fp = (const float4*)&s_feats[token*FPAD];
            const float4* sp = (const float4*)&s_slots[slot*FPAD];
            float d0=0.f,d1=0.f,d2=0.f,d3=0.f;
            #pragma unroll 8
            for (int c=0;c<32;c++){
                float4 f=fp[c], s=sp[c];
                d0=fmaf(f.x,s.x,d0); d1=fmaf(f.y,s.y,d1);
                d2=fmaf(f.z,s.z,d2); d3=fmaf(f.w,s.w,d3);
            }
            float dot=(d0+d1)+(d2+d3);
            float f2n=s_f2[token], frn=s_fr[token], dens=s_dn[token];
            float s2k=s_s2[slot], srk=s_sr[slot];
            int lvl = slot - (slot/3)*3;
            float basel=(lvl==0)?2.f:((lvl==1)?1.f:0.5f);
            float mod = rs*(dens-0.5f);
            float diff2 = fmaxf(f2n + s2k - 2.f*dot, 0.f);
            float xn = fminf(f2n, 1.f-1e-5f);
            float yn = fminf(s2k, 1.f-1e-5f);
            float den = fmaxf((1.f-xn)*(1.f-yn), 1e-6f);
            float arg = fmaxf(1.f + 2.f*diff2/den, 1.f+1e-6f);
            float hd = acoshf(arg);
            float rd = fabsf(frn-srk);
            float scv = fminf(fmaxf(basel+mod,0.3f),3.f);
            s_attn[token*APAD + slot] = (-hd - 3.f*rd)*scv*10.f;   // /TAU
        }
        __syncthreads();
        // ---- softmax per token (warp 0) ----
        if (tid<32){
            float m=-1e30f;
            #pragma unroll
            for (int k=0;k<NSLOT;k++) m=fmaxf(m, s_attn[tid*APAD+k]);
            float ssum=0.f;
            #pragma unroll
            for (int k=0;k<NSLOT;k++){
                float e=expf(s_attn[tid*APAD+k]-m);
                s_attn[tid*APAD+k]=e; ssum+=e;
            }
            float inv=1.f/ssum;
            #pragma unroll
            for (int k=0;k<NSLOT;k++) s_attn[tid*APAD+k]*=inv;
        }
        __syncthreads();
        // ---- rowsum partial ----
        if (tid<NSLOT){
            float r=0.f;
            #pragma unroll 8
            for (int n=0;n<32;n++) r += s_attn[n*APAD+tid];
            rsum += r;
        }
        // ---- phase 2a: coalesced attn_out stores ----
        if (tid < 192){
            int k = tid>>3, q = tid&7;
            float4 v;
            v.x = s_attn[(q*4+0)*APAD + k];
            v.y = s_attn[(q*4+1)*APAD + k];
            v.z = s_attn[(q*4+2)*APAD + k];
            v.w = s_attn[(q*4+3)*APAD + k];
            *(float4*)&attn_out[((size_t)b*NSLOT+k)*NNP + nbase + ch*32 + q*4] = v;
        }
        // ---- phase 2b: upd mini-GEMM ----
        #pragma unroll
        for (int p=0;p<3;p++){
            int idx = p*256 + tid;
            int k = idx>>5, h4 = idx&31;
            float4 a4 = (p==0)?acc0:((p==1)?acc1:acc2);
            #pragma unroll 8
            for (int n=0;n<32;n++){
                float av = s_attn[n*APAD + k];
                float4 fv = ((const float4*)&s_feats[n*FPAD])[h4];
                a4.x=fmaf(av,fv.x,a4.x); a4.y=fmaf(av,fv.y,a4.y);
                a4.z=fmaf(av,fv.z,a4.z); a4.w=fmaf(av,fv.w,a4.w);
            }
            if (p==0) acc0=a4; else if (p==1) acc1=a4; else acc2=a4;
        }
    }
    // ---- finalize ----
    if (tid<NSLOT) atomicAdd(&g_rowsum[b*NSLOT+tid], rsum);
    #pragma unroll
    for (int p=0;p<3;p++){
        int idx = p*256 + tid;
        int k = idx>>5, h4 = idx&31;
        float4 a4 = (p==0)?acc0:((p==1)?acc1:acc2);
        float* up = g_upd + ((size_t)b*NSLOT+k)*HD + h4*4;
        atomicAdd(up+0,a4.x); atomicAdd(up+1,a4.y);
        atomicAdd(up+2,a4.z); atomicAdd(up+3,a4.w);
    }
}

// ======================= GRU + MLP + renorm (warp-row gi, coalesced) =======================
__device__ __forceinline__ float blksum128(float v, volatile float* red){
    #pragma unroll
    for (int o=16;o;o>>=1) v += __shfl_xor_sync(0xffffffffu,v,o);
    __syncthreads();
    if ((threadIdx.x&31)==0) red[threadIdx.x>>5]=v;
    __syncthreads();
    return red[0]+red[1]+red[2]+red[3];
}

__global__ void __launch_bounds__(128) gru_kernel(const float* __restrict__ obj_dirs,
    const float* __restrict__ gru_wi, const float* __restrict__ gru_bi,
    const float* __restrict__ mlp_w1, const float* __restrict__ mlp_b1,
    const float* __restrict__ mlp_w2, const float* __restrict__ mlp_b2,
    const float* __restrict__ norm_g, const float* __restrict__ norm_b,
    float* __restrict__ slots_out)
{
    __shared__ float s_buf[HD];
    __shared__ float s_gi[3*HD];
    __shared__ float s_red[4];
    const int b = blockIdx.x >> 3, o = blockIdx.x & 7;
    const int h = threadIdx.x, w = h>>5, l = h&31;
    float ou=0.f;
    #pragma unroll
    for (int lv=0;lv<3;lv++){
        int k=o*3+lv;
        ou += g_upd[((size_t)b*NSLOT+k)*HD + h] / (g_rowsum[b*NSLOT+k]+1e-8f);
    }
    s_buf[h]=ou; __syncthreads();
    #pragma unroll
    for (int lv=0;lv<3;lv++){
        int k=o*3+lv;
        g_upd[((size_t)b*NSLOT+k)*HD + h]=0.f;
        if (h==lv) g_rowsum[b*NSLOT+k]=0.f;
    }
    {
        float4 ob = ((const float4*)s_buf)[l];
        for (int m=0;m<96;m++){
            int r = w*96 + m;
            float4 wv = ((const float4*)(gru_wi + (size_t)r*HD))[l];
            float p = ob.x*wv.x + ob.y*wv.y + ob.z*wv.z + ob.w*wv.w;
            #pragma unroll
            for (int of=16;of;of>>=1) p += __shfl_xor_sync(0xffffffffu,p,of);
            if (l==0) s_gi[r] = p + gru_bi[r];
        }
    }
    __syncthreads();
    float hr=g_gh[o*3*HD + h], hz=g_gh[o*3*HD + HD + h], hn=g_gh[o*3*HD + 2*HD + h];
    float rr=sigmoidf(s_gi[h]+hr);
    float z =sigmoidf(s_gi[HD+h]+hz);
    float nnv=tanhf(s_gi[2*HD+h]+rr*hn);
    float oldh=obj_dirs[o*HD+h];
    float nd=(1.f-z)*nnv + z*oldh;
    float s = blksum128(nd, s_red);
    float q = blksum128(nd*nd, s_red);
    float mu=s*(1.f/HD), var=q*(1.f/HD)-mu*mu;
    float ln=(nd-mu)*rsqrtf(var+1e-5f)*norm_g[h]+norm_b[h];
    __syncthreads(); s_buf[h]=ln; __syncthreads();
    float m1=mlp_b1[h];
    {
        const float* w1=mlp_w1;
        #pragma unroll 8
        for (int hh=0;hh<HD;hh++) m1=fmaf(s_buf[hh],w1[(size_t)hh*HD+h],m1);
    }
    m1=geluf(m1);
    __syncthreads(); s_buf[h]=m1; __syncthreads();
    float m2=mlp_b2[h];
    {
        const float* w2=mlp_w2;
        #pragma unroll 8
        for (int hh=0;hh<HD;hh++) m2=fmaf(s_buf[hh],w2[(size_t)hh*HD+h],m2);
    }
    float nd2 = nd + 0.2f*m2;
    float q2 = blksum128(nd2*nd2, s_red);
    float nrm = fmaxf(sqrtf(q2),1e-12f);
    float ndn = nd2/nrm;
    float qn = q2/(nrm*nrm);
    const float radii[3]={0.2f,0.5f,0.8f};
    #pragma unroll
    for (int lv=0;lv<3;lv++){
        float r=radii[lv];
        float v=ndn*r;
        size_t idx=((size_t)b*NSLOT + o*3+lv)*HD + h;
        g_slots[idx]=v;
        slots_out[idx]=v;
    }
    if (h<3){
        float r=radii[h];
        float s2v=qn*r*r;
        g_s2[b*NSLOT + o*3 + h]=s2v;
        g_sr[b*NSLOT + o*3 + h]=sqrtf(s2v);
    }
}

// ======================= host launch =======================
extern "C" void kernel_launch(void* const* d_in, const int* in_sizes, int n_in,
                              void* d_out, int out_size)
{
    const float* x      = (const float*)d_in[0];
    const float* fe_w1  = (const float*)d_in[1];
    const float* fe_b1  = (const float*)d_in[2];
    const float* ln1_g  = (const float*)d_in[3];
    const float* ln1_b  = (const float*)d_in[4];
    const float* fe_w2  = (const float*)d_in[5];
    const float* fe_b2  = (const float*)d_in[6];
    const float* ln2_g  = (const float*)d_in[7];
    const float* ln2_b  = (const float*)d_in[8];
    const float* hp_w   = (const float*)d_in[9];
    const float* hp_b   = (const float*)d_in[10];
    const float* obj_dirs = (const float*)d_in[11];
    const float* radius_scale = (const float*)d_in[12];
    const float* gru_wi = (const float*)d_in[13];
    const float* gru_wh = (const float*)d_in[14];
    const float* gru_bi = (const float*)d_in[15];
    const float* gru_bh = (const float*)d_in[16];
    const float* mlp_w1 = (const float*)d_in[17];
    const float* mlp_b1 = (const float*)d_in[18];
    const float* mlp_w2 = (const float*)d_in[19];
    const float* mlp_b2 = (const float*)d_in[20];
    const float* norm_g = (const float*)d_in[21];
    const float* norm_b = (const float*)d_in[22];

    float* out = (float*)d_out;
    float* slots_out = out;                                   // [16,24,128]
    float* attn_out  = out + BB*NSLOT*HD;                     // [16,24,2048]
    float* dens_out  = attn_out + (size_t)BB*NSLOT*NNP;       // [16,2048]

    size_t encSmem = (size_t)ENC_SMEM_FLOATS*sizeof(float);   // 212,992 B
    cudaFuncSetAttribute(enc_kernel, cudaFuncAttributeMaxDynamicSharedMemorySize, (int)encSmem);

    // Launch order: attn_kernel is the 0-based 4th launch (ncu capture point).
    enc_kernel<<<BB*NNP/64, 512, encSmem>>>(x, fe_w1, fe_b1, ln1_g, ln1_b,
                                            fe_w2, fe_b2, ln2_g, ln2_b, hp_w, hp_b);   // 0
    prep_kernel<<<BB*NNP*IND/2/256, 256>>>(x, obj_dirs);                               // 1
    {
        dim3 g(NNP/64, BB);
        densfeats_kernel<<<g, 256>>>(dens_out);                                        // 2
    }
    attn_kernel<<<BB*16, 256>>>(radius_scale, attn_out);                               // 3 <- profiled
    gh_kernel<<<NOBJ, 256>>>(obj_dirs, gru_wh, gru_bh);                                // 4
    gru_kernel<<<BB*NOBJ, 128>>>(obj_dirs, gru_wi, gru_bi,
                                 mlp_w1, mlp_b1, mlp_w2, mlp_b2,
                                 norm_g, norm_b, slots_out);                           // 5
    for (int it=1; it<NITER; it++){
        attn_kernel<<<BB*16, 256>>>(radius_scale, attn_out);
        gru_kernel<<<BB*NOBJ, 128>>>(obj_dirs, gru_wi, gru_bi,
                                     mlp_w1, mlp_b1, mlp_w2, mlp_b2,
                                     norm_g, norm_b, slots_out);
    }
}